// round 13
// baseline (speedup 1.0000x reference)
#include <cuda_runtime.h>
#include <cuda_fp16.h>

#define FULL 0xffffffffu
typedef unsigned long long u64;
typedef unsigned int u32;

__device__ __forceinline__ float lrelu(float v){ return v > 0.f ? v : 0.1f*v; }
__device__ __forceinline__ float tanha(float v){
  float r; asm("tanh.approx.f32 %0, %1;" : "=f"(r) : "f"(v)); return r;
}
__device__ __forceinline__ float sigma(float v){
  return fmaf(tanha(0.5f*v), 0.5f, 0.5f);
}
__device__ __forceinline__ u64 pk2(float lo, float hi){
  u64 r; asm("mov.b64 %0,{%1,%2};" : "=l"(r) : "f"(lo), "f"(hi)); return r;
}
__device__ __forceinline__ float2 up2(u64 v){
  float2 r; asm("mov.b64 {%0,%1},%2;" : "=f"(r.x), "=f"(r.y) : "l"(v)); return r;
}
__device__ __forceinline__ u64 ffma2(u64 a, u64 b, u64 c){
  u64 d; asm("fma.rn.f32x2 %0,%1,%2,%3;" : "=l"(d) : "l"(a), "l"(b), "l"(c)); return d;
}
__device__ __forceinline__ u64 fadd2(u64 a, u64 b){
  u64 d; asm("add.rn.f32x2 %0,%1,%2;" : "=l"(d) : "l"(a), "l"(b)); return d;
}

// ---- dynamic smem: weights region (+packed conv, LUT) then WPB workspaces ----
#define oWEW   0      // 16 rows stride 20
#define oWEB   320
#define oAW    336    // 16 rows stride 17
#define oAB    608
#define oC1B   624
#define oC2B   640
#define oC3B   656
#define oWIH   672    // 18 rows stride 20
#define oBIH   1032
#define oWHH   1052   // 18 rows stride 7
#define oBHH   1178
#define oFC3   1196   // 108
#define oFC3B  1304
#define oCP    1312   // packed conv weights: 16 rows stride 162, [c*10]: wo,w2a,w2b,w2c,w30..w34,pad
#define oLUT   3904   // u16[2400] = 1200 floats
#define W_TOT  5104   // 16B-aligned

struct WS {
  float xe[800];    // embed out, flat [l*16+c]; xr[c][l] view = xe[c*50+l]
  float attn[800];  // tanh attention [l][16]; ALSO x-staging; ALSO eM overflow in D
  float x4[304];    // GRU outputs flat [l*6+h]
  float p2a[52];    // per-j prefix sums over h (inv-scaled in D)
  float p4a[52];
  float s6a[52];
  float bred[104];  // per-lane (la,ha,lb,hb) bin partials
  float inv[52];
  float feat[56];
  float pad[48];
};                   // 2320 floats

#define WPB 8
#define SMEM_FLOATS (W_TOT + WPB*2320)
#define SMEM_BYTES  (SMEM_FLOATS*4)

__global__ __launch_bounds__(WPB*32, 2) void nn_fused_kernel(
    const float* __restrict__ x,
    const float* __restrict__ we_w, const float* __restrict__ we_b,
    const float* __restrict__ attn_w, const float* __restrict__ attn_b,
    const float* __restrict__ c1w, const float* __restrict__ c1b,
    const float* __restrict__ c2w, const float* __restrict__ c2b,
    const float* __restrict__ c3w, const float* __restrict__ c3b,
    const float* __restrict__ wih, const float* __restrict__ whh,
    const float* __restrict__ bih, const float* __restrict__ bhh,
    const float* __restrict__ fc3w, const float* __restrict__ fc3b,
    float* __restrict__ out, int B)
{
  extern __shared__ float dyn[];
  const int tid = threadIdx.x;
  const int NT = WPB*32;

  // ---- cooperative weight load ----
  for (int i=tid;i<320;i+=NT)  dyn[oWEW + i] = we_w[i];
  for (int i=tid;i<256;i+=NT)  dyn[oAW  + (i>>4)*17+(i&15)] = attn_w[i];
  for (int i=tid;i<288;i+=NT)  dyn[oWIH + (i>>4)*20+(i&15)] = wih[i];
  for (int i=tid;i<108;i+=NT)  dyn[oWHH + (i/6)*7+(i%6)]    = whh[i];
  for (int i=tid;i<108;i+=NT)  dyn[oFC3 + i] = fc3w[i];
  // packed conv weights
  for (int i=tid;i<256;i+=NT){ int j=i>>4, c=i&15; dyn[oCP + j*162 + c*10] = c1w[i]; }
  for (int i=tid;i<768;i+=NT){ int j=i/48, m=i-j*48, c=m/3, k=m-c*3; dyn[oCP + j*162 + c*10 + 1 + k] = c2w[i]; }
  for (int i=tid;i<1280;i+=NT){ int j=i/80, m=i-j*80, c=m/5, k=m-c*5; dyn[oCP + j*162 + c*10 + 4 + k] = c3w[i]; }
  {
    unsigned short* LUT = (unsigned short*)(dyn + oLUT);
    for (int i=tid;i<2400;i+=NT) LUT[i] = (unsigned short)((i/48)*16 + (i&15));
  }
  if (tid<16){ dyn[oWEB+tid]=we_b[tid]; dyn[oAB+tid]=attn_b[tid];
               dyn[oC1B+tid]=c1b[tid]; dyn[oC2B+tid]=c2b[tid]; dyn[oC3B+tid]=c3b[tid]; }
  if (tid>=32 && tid<50){ dyn[oBIH+tid-32]=bih[tid-32]; dyn[oBHH+tid-32]=bhh[tid-32]; }
  if (tid==50){ dyn[oFC3B]=fc3b[0]; dyn[oFC3B+1]=fc3b[1]; }
  __syncthreads();

  const int w    = tid >> 5;
  const int lane = tid & 31;
  WS& s = *((WS*)(dyn + W_TOT) + w);
  const unsigned short* LUT = (const unsigned short*)(dyn + oLUT);
  const int b = blockIdx.x*WPB + w;
  if (b >= B) return;

  // ---- stage x [50][20] into attn..x4 region via float4 ----
  float* xstage = s.attn;
  {
    const float4* xb4 = (const float4*)(x + (size_t)b*1000);
    float4* r4 = (float4*)xstage;
    for (int i=lane;i<250;i+=32) r4[i] = xb4[i];
  }
  __syncwarp();

  // ---- Phase A: xe[l][c] = x[l,:] . we_w[c,:] + b[c] ----
  {
    const int c = lane & 15;
    float wr[20];
    const float4* wp = (const float4*)&dyn[oWEW + c*20];
    #pragma unroll
    for (int q=0;q<5;q++){ float4 v = wp[q]; wr[4*q]=v.x; wr[4*q+1]=v.y; wr[4*q+2]=v.z; wr[4*q+3]=v.w; }
    const float bc = dyn[oWEB+c];
    for (int k=lane;k<800;k+=32){
      const int l = k >> 4;
      const float4* rp = (const float4*)&xstage[l*20];
      float acc = bc;
      #pragma unroll
      for (int q=0;q<5;q++){
        float4 v = rp[q];
        acc = fmaf(v.x, wr[4*q], acc); acc = fmaf(v.y, wr[4*q+1], acc);
        acc = fmaf(v.z, wr[4*q+2], acc); acc = fmaf(v.w, wr[4*q+3], acc);
      }
      s.xe[k] = acc;
    }
  }
  __syncwarp();

  // ---- Phase B (f32x2 + MUFU tanh): attn[l][c], pairs of l ----
  {
    const int c  = lane & 15;
    const int ph = lane >> 4;
    u64 arp[16];
    #pragma unroll
    for (int cc=0;cc<16;cc++){ float v = dyn[oAW + c*17+cc]; arp[cc] = pk2(v,v); }
    const float ab = dyn[oAB+c];
    for (int p = ph; p < 25; p += 2){
      const int l = 2*p;
      u64 accA = pk2(ab, ab), accB = 0ull;
      #pragma unroll
      for (int cc=0;cc<8;cc++){
        accA = ffma2(arp[cc],   *(const u64*)&s.xe[cc*50+l],     accA);
        accB = ffma2(arp[cc+8], *(const u64*)&s.xe[(cc+8)*50+l], accB);
      }
      float2 v = up2(fadd2(accA, accB));
      s.attn[l*16+c]    = tanha(v.x);
      s.attn[l*16+16+c] = tanha(v.y);
    }
  }
  __syncwarp();

  // ---- Phase C: GRU with fused input pre-gates (MUFU nonlinearities) ----
  {
    const int g = lane < 18 ? lane : 0;
    float wr[16];
    {
      const float4* wp = (const float4*)&dyn[oWIH + g*20];
      #pragma unroll
      for (int q=0;q<4;q++){ float4 v=wp[q]; wr[4*q]=v.x; wr[4*q+1]=v.y; wr[4*q+2]=v.z; wr[4*q+3]=v.w; }
    }
    float wh[6];
    #pragma unroll
    for (int i=0;i<6;i++) wh[i]=dyn[oWHH + g*7+i];
    const float bg  = dyn[oBIH+g];
    const float bhg = dyn[oBHH+g];
    float h0=0,h1=0,h2=0,h3=0,h4=0,h5=0, hm=0;
    for (int l=0;l<50;l++){
      const float4* xp = (const float4*)&s.xe[l*16];
      float gi = bg;
      #pragma unroll
      for (int q=0;q<4;q++){
        float4 xv = xp[q];
        gi = fmaf(xv.x, wr[4*q], gi); gi = fmaf(xv.y, wr[4*q+1], gi);
        gi = fmaf(xv.z, wr[4*q+2], gi); gi = fmaf(xv.w, wr[4*q+3], gi);
      }
      float gh = bhg;
      gh = fmaf(wh[0],h0,gh); gh = fmaf(wh[1],h1,gh); gh = fmaf(wh[2],h2,gh);
      gh = fmaf(wh[3],h3,gh); gh = fmaf(wh[4],h4,gh); gh = fmaf(wh[5],h5,gh);
      const float a   = gi + gh;
      const float ar  = __shfl_sync(FULL, a,  lane);
      const float az  = __shfl_sync(FULL, a,  lane+6);
      const float gin = __shfl_sync(FULL, gi, lane+12);
      const float ghn = __shfl_sync(FULL, gh, lane+12);
      float hn = 0.f;
      if (lane < 6){
        const float r = sigma(ar);
        const float z = sigma(az);
        const float n = tanha(fmaf(r, ghn, gin));
        hn = (1.f - z)*n + z*hm;
        hm = hn;
        s.x4[l*6+lane] = hn;
      }
      h0=__shfl_sync(FULL,hn,0); h1=__shfl_sync(FULL,hn,1); h2=__shfl_sync(FULL,hn,2);
      h3=__shfl_sync(FULL,hn,3); h4=__shfl_sync(FULL,hn,4); h5=__shfl_sync(FULL,hn,5);
    }
  }
  __syncwarp();

  // ---- Phase E (channel-split halves, l-tile=5, packed weights) ----
  {
    const int j    = lane & 15;
    const int half = lane >> 4;
    const int cbase = half*8;
    const int jb = j*162;
    const float b1 = dyn[oC1B+j], b2 = dyn[oC2B+j], b3 = dyn[oC3B+j];
    float xc1 = 0.f, xc2 = 0.f, xc3 = 0.f;
    #pragma unroll
    for (int t10=0;t10<10;t10++){
      const int l0 = t10*5;
      float acc1[5], acc2[5], acc3[5];
      #pragma unroll
      for (int lt=0;lt<5;lt++){ acc1[lt]=0.f; acc2[lt]=0.f; acc3[lt]=0.f; }
      #pragma unroll
      for (int cc=0;cc<8;cc++){
        const int c = cbase+cc;
        const float* xr = &s.xe[c*50];
        float win[9];               // covers t = l0-2 .. l0+6
        #pragma unroll
        for (int off=0;off<9;off++){
          const int t = l0 + off - 2;
          win[off] = (t>=0 && t<50) ? xr[t] : 0.f;
        }
        const float2 f0 = *(const float2*)&dyn[oCP + jb + c*10];     // wo, w2a
        const float2 f1 = *(const float2*)&dyn[oCP + jb + c*10+2];   // w2b, w2c
        const float2 f2 = *(const float2*)&dyn[oCP + jb + c*10+4];   // w30, w31
        const float2 f3 = *(const float2*)&dyn[oCP + jb + c*10+6];   // w32, w33
        const float2 f4 = *(const float2*)&dyn[oCP + jb + c*10+8];   // w34, -
        #pragma unroll
        for (int lt=0;lt<5;lt++){
          acc1[lt] = fmaf(f0.x, win[lt+2], acc1[lt]);
          acc2[lt] = fmaf(f0.y, win[lt+1], fmaf(f1.x, win[lt+2], fmaf(f1.y, win[lt+3], acc2[lt])));
          float a = acc3[lt];
          a = fmaf(f2.x, win[lt],   a);
          a = fmaf(f2.y, win[lt+1], a);
          a = fmaf(f3.x, win[lt+2], a);
          a = fmaf(f3.y, win[lt+3], a);
          a = fmaf(f4.x, win[lt+4], a);
          acc3[lt] = a;
        }
      }
      #pragma unroll
      for (int lt=0;lt<5;lt++){
        const int l = l0+lt;
        float v1 = acc1[lt] + __shfl_xor_sync(FULL, acc1[lt], 16) + b1;
        float v2 = acc2[lt] + __shfl_xor_sync(FULL, acc2[lt], 16) + b2;
        float v3 = acc3[lt] + __shfl_xor_sync(FULL, acc3[lt], 16) + b3;
        const int i1 = j*50+l, i2 = (16+j)*50+l, i3 = (32+j)*50+l;
        xc1 = fmaf(lrelu(v1), s.attn[LUT[i1]], xc1);
        xc2 = fmaf(lrelu(v2), s.attn[LUT[i2]], xc2);
        xc3 = fmaf(lrelu(v3), s.attn[LUT[i3]], xc3);
      }
    }
    if (half==0){ s.feat[j]=xc1; s.feat[16+j]=xc2; s.feat[32+j]=xc3; }
  }
  __syncwarp();

  // ---- Phase D (fused): half2 score cache, f32x2 scores, inv folded into PS ----
  {
    u32* eM = (u32*)s.xe;      // [25][53] u32; 1325 u32 < xe+attn (1600)
    if (lane < 25){
      float p2ja, p4ja, s6ja, p2jb, p4jb, s6jb;
      {
        const float2 a0=*(const float2*)&s.x4[lane*6], a1=*(const float2*)&s.x4[lane*6+2], a2=*(const float2*)&s.x4[lane*6+4];
        p2ja = a0.x+a0.y; p4ja = p2ja + a1.x+a1.y; s6ja = p4ja + a2.x+a2.y;
        const int jb6 = (lane+25)*6;
        const float2 b0=*(const float2*)&s.x4[jb6], b1=*(const float2*)&s.x4[jb6+2], b2=*(const float2*)&s.x4[jb6+4];
        p2jb = b0.x+b0.y; p4jb = p2jb + b1.x+b1.y; s6jb = p4jb + b2.x+b2.y;
      }
      const int ja = lane, jb = lane+25;
      u64 XA01, XA23, XA45, XB01, XB23, XB45;
      {
        XA01 = pk2(s.x4[ja], s.x4[50+ja]);
        XA23 = pk2(s.x4[100+ja], s.x4[150+ja]);
        XA45 = pk2(s.x4[200+ja], s.x4[250+ja]);
        XB01 = pk2(s.x4[jb], s.x4[50+jb]);
        XB23 = pk2(s.x4[100+jb], s.x4[150+jb]);
        XB45 = pk2(s.x4[200+jb], s.x4[250+jb]);
      }
      float csa=0.f, csb=0.f;
      for (int i=0;i<50;i++){
        const u64 P0 = *(const u64*)&s.x4[i*6];
        const u64 P1 = *(const u64*)&s.x4[i*6+2];
        const u64 P2 = *(const u64*)&s.x4[i*6+4];
        u64 A = ffma2(P0, XA01, 0ull); A = ffma2(P1, XA23, A); A = ffma2(P2, XA45, A);
        u64 Bv = ffma2(P0, XB01, 0ull); Bv = ffma2(P1, XB23, Bv); Bv = ffma2(P2, XB45, Bv);
        const float2 av = up2(A), bv = up2(Bv);
        const float sa = av.x + av.y;
        const float sb = bv.x + bv.y;
        const float ea = __expf(sa*(1.f/6.f));
        const float eb = __expf(sb*(1.f/6.f));
        csa += ea; csb += eb;
        __half2 hp = __floats2half2_rn(ea, eb);
        eM[lane*53+i] = *(u32*)&hp;
      }
      const float iva = __fdividef(1.f, csa);
      const float ivb = __fdividef(1.f, csb);
      s.p2a[ja] = p2ja*iva; s.p4a[ja] = p4ja*iva; s.s6a[ja] = s6ja*iva;
      s.p2a[jb] = p2jb*ivb; s.p4a[jb] = p4jb*ivb; s.s6a[jb] = s6jb*ivb;
    }
    __syncwarp();
    if (lane < 25){
      const int ia = lane, ib = lane+25;
      const int m = (ia*6) % 50;
      const float* PS = (m==48) ? s.p2a : (m==46) ? s.p4a : s.s6a;
      float la=0.f, ha=0.f, lb=0.f, hb=0.f;
      for (int j=0;j<25;j++){
        const u32 pa = eM[j*53+ia];
        const u32 pb = eM[j*53+ib];
        const float2 ea2 = __half22float2(*(const __half2*)&pa);
        const float2 eb2 = __half22float2(*(const __half2*)&pb);
        const float ps0 = PS[j],    hi0 = s.s6a[j]    - ps0;
        const float ps1 = PS[j+25], hi1 = s.s6a[j+25] - ps1;
        la = fmaf(ea2.x, ps0, la); ha = fmaf(ea2.x, hi0, ha);
        la = fmaf(ea2.y, ps1, la); ha = fmaf(ea2.y, hi1, ha);
        lb = fmaf(eb2.x, ps0, lb); hb = fmaf(eb2.x, hi0, hb);
        lb = fmaf(eb2.y, ps1, lb); hb = fmaf(eb2.y, hi1, hb);
      }
      *(float4*)&s.bred[lane*4] = make_float4(la, ha, lb, hb);
    }
    __syncwarp();
    if (lane < 6){
      float acc = 0.f;
      for (int L=0;L<25;L++){
        const int g0 = (L*6)/50;
        const float4 v = *(const float4*)&s.bred[L*4];
        if (g0==lane)   acc += v.x;
        if (g0==lane-1) acc += v.y;
        if (g0==lane-3) acc += v.z;
        if (g0==lane-4) acc += v.w;
      }
      s.feat[48+lane] = acc;
    }
  }
  __syncwarp();

  // ---- FC3 (parallel over lanes + shfl reduce) ----
  {
    float a0 = 0.f, a1 = 0.f;
    if (lane < 27){
      const float fa = s.feat[lane], fb = s.feat[lane+27];
      a0 = fa*dyn[oFC3+lane]    + fb*dyn[oFC3+lane+27];
      a1 = fa*dyn[oFC3+54+lane] + fb*dyn[oFC3+54+lane+27];
    }
    #pragma unroll
    for (int off=16; off>=1; off>>=1){
      a0 += __shfl_xor_sync(FULL, a0, off);
      a1 += __shfl_xor_sync(FULL, a1, off);
    }
    if (lane == 0){
      out[(size_t)b*2]   = a0 + dyn[oFC3B];
      out[(size_t)b*2+1] = a1 + dyn[oFC3B+1];
    }
  }
}

extern "C" void kernel_launch(void* const* d_in, const int* in_sizes, int n_in,
                              void* d_out, int out_size) {
  const float* x      = (const float*)d_in[0];
  const float* we_w   = (const float*)d_in[1];
  const float* we_b   = (const float*)d_in[2];
  const float* attn_w = (const float*)d_in[3];
  const float* attn_b = (const float*)d_in[4];
  const float* c1w    = (const float*)d_in[5];
  const float* c1b    = (const float*)d_in[6];
  const float* c2w    = (const float*)d_in[7];
  const float* c2b    = (const float*)d_in[8];
  const float* c3w    = (const float*)d_in[9];
  const float* c3b    = (const float*)d_in[10];
  const float* wih    = (const float*)d_in[11];
  const float* whh    = (const float*)d_in[12];
  const float* bih    = (const float*)d_in[13];
  const float* bhh    = (const float*)d_in[14];
  const float* fc3w   = (const float*)d_in[15];
  const float* fc3b   = (const float*)d_in[16];
  float* out = (float*)d_out;

  const int B = in_sizes[0] / 1000;
  const int blocks = (B + WPB - 1) / WPB;
  cudaFuncSetAttribute(nn_fused_kernel, cudaFuncAttributeMaxDynamicSharedMemorySize, SMEM_BYTES);
  nn_fused_kernel<<<blocks, WPB*32, SMEM_BYTES>>>(x, we_w, we_b, attn_w, attn_b,
                                  c1w, c1b, c2w, c2b, c3w, c3b,
                                  wih, whh, bih, bhh, fc3w, fc3b, out, B);
}

// round 14
// speedup vs baseline: 1.0786x; 1.0786x over previous
#include <cuda_runtime.h>
#include <cuda_fp16.h>

#define FULL 0xffffffffu
typedef unsigned long long u64;
typedef unsigned int u32;

__device__ __forceinline__ float lrelu(float v){ return v > 0.f ? v : 0.1f*v; }
__device__ __forceinline__ float tanha(float v){
  float r; asm("tanh.approx.f32 %0, %1;" : "=f"(r) : "f"(v)); return r;
}
__device__ __forceinline__ float sigma(float v){
  return fmaf(tanha(0.5f*v), 0.5f, 0.5f);
}
__device__ __forceinline__ u64 pk2(float lo, float hi){
  u64 r; asm("mov.b64 %0,{%1,%2};" : "=l"(r) : "f"(lo), "f"(hi)); return r;
}
__device__ __forceinline__ float2 up2(u64 v){
  float2 r; asm("mov.b64 {%0,%1},%2;" : "=f"(r.x), "=f"(r.y) : "l"(v)); return r;
}
__device__ __forceinline__ u64 ffma2(u64 a, u64 b, u64 c){
  u64 d; asm("fma.rn.f32x2 %0,%1,%2,%3;" : "=l"(d) : "l"(a), "l"(b), "l"(c)); return d;
}
__device__ __forceinline__ u64 fadd2(u64 a, u64 b){
  u64 d; asm("add.rn.f32x2 %0,%1,%2;" : "=l"(d) : "l"(a), "l"(b)); return d;
}

// ---- dynamic smem: weights region (+LUT) then WPB per-warp workspaces ----
#define oWEW   0      // 16 rows stride 20
#define oWEB   320
#define oAW    336    // 16 rows stride 17
#define oAB    608
#define oC1W   624    // 16 rows stride 17
#define oC1B   896
#define oC2W   912    // 16 rows stride 49, [j][c*3+k]
#define oC2B   1696
#define oC3W   1712   // 16 rows stride 81, [j][c*5+k]
#define oC3B   3008
#define oWIH   3024   // 18 rows stride 20
#define oBIH   3384
#define oWHH   3404   // 18 rows stride 7
#define oBHH   3530
#define oFC3   3552   // 108
#define oFC3B  3660
#define oLUT   3664   // u16[2400] = 1200 floats
#define W_TOT  4864   // 16B-aligned

struct WS {
  float xe[800];    // embed out, flat [l*16+c]; xr[c][l] view = xe[c*50+l]
  float attn[800];  // tanh attention [l][16]; ALSO x-staging; ALSO eM overflow in D
  float x4[304];    // GRU outputs flat [l*6+h]
  float p2a[52];    // per-j prefix sums over h (inv-scaled in D)
  float p4a[52];
  float s6a[52];
  float bred[104];  // per-lane (la,ha,lb,hb) bin partials
  float inv[52];
  float feat[56];
  float pad[48];
};                   // 2320 floats

#define WPB 8
#define SMEM_FLOATS (W_TOT + WPB*2320)
#define SMEM_BYTES  (SMEM_FLOATS*4)

__global__ __launch_bounds__(WPB*32, 2) void nn_fused_kernel(
    const float* __restrict__ x,
    const float* __restrict__ we_w, const float* __restrict__ we_b,
    const float* __restrict__ attn_w, const float* __restrict__ attn_b,
    const float* __restrict__ c1w, const float* __restrict__ c1b,
    const float* __restrict__ c2w, const float* __restrict__ c2b,
    const float* __restrict__ c3w, const float* __restrict__ c3b,
    const float* __restrict__ wih, const float* __restrict__ whh,
    const float* __restrict__ bih, const float* __restrict__ bhh,
    const float* __restrict__ fc3w, const float* __restrict__ fc3b,
    float* __restrict__ out, int B)
{
  extern __shared__ float dyn[];
  const int tid = threadIdx.x;
  const int NT = WPB*32;

  // ---- cooperative weight load ----
  for (int i=tid;i<320;i+=NT)  dyn[oWEW + i] = we_w[i];
  for (int i=tid;i<256;i+=NT)  dyn[oAW  + (i>>4)*17+(i&15)] = attn_w[i];
  for (int i=tid;i<256;i+=NT)  dyn[oC1W + (i>>4)*17+(i&15)] = c1w[i];
  for (int i=tid;i<768;i+=NT)  dyn[oC2W + (i/48)*49+(i%48)] = c2w[i];
  for (int i=tid;i<1280;i+=NT) dyn[oC3W + (i/80)*81+(i%80)] = c3w[i];
  for (int i=tid;i<288;i+=NT)  dyn[oWIH + (i>>4)*20+(i&15)] = wih[i];
  for (int i=tid;i<108;i+=NT)  dyn[oWHH + (i/6)*7+(i%6)]    = whh[i];
  for (int i=tid;i<108;i+=NT)  dyn[oFC3 + i] = fc3w[i];
  {
    unsigned short* LUT = (unsigned short*)(dyn + oLUT);
    for (int i=tid;i<2400;i+=NT) LUT[i] = (unsigned short)((i/48)*16 + (i&15));
  }
  if (tid<16){ dyn[oWEB+tid]=we_b[tid]; dyn[oAB+tid]=attn_b[tid];
               dyn[oC1B+tid]=c1b[tid]; dyn[oC2B+tid]=c2b[tid]; dyn[oC3B+tid]=c3b[tid]; }
  if (tid>=32 && tid<50){ dyn[oBIH+tid-32]=bih[tid-32]; dyn[oBHH+tid-32]=bhh[tid-32]; }
  if (tid==50){ dyn[oFC3B]=fc3b[0]; dyn[oFC3B+1]=fc3b[1]; }
  __syncthreads();

  const int w    = tid >> 5;
  const int lane = tid & 31;
  WS& s = *((WS*)(dyn + W_TOT) + w);
  const unsigned short* LUT = (const unsigned short*)(dyn + oLUT);
  const int b = blockIdx.x*WPB + w;
  if (b >= B) return;

  // ---- stage x [50][20] into attn..x4 region via float4 ----
  float* xstage = s.attn;
  {
    const float4* xb4 = (const float4*)(x + (size_t)b*1000);
    float4* r4 = (float4*)xstage;
    for (int i=lane;i<250;i+=32) r4[i] = xb4[i];
  }
  __syncwarp();

  // ---- Phase A: xe[l][c] = x[l,:] . we_w[c,:] + b[c] ----
  {
    const int c = lane & 15;
    float wr[20];
    const float4* wp = (const float4*)&dyn[oWEW + c*20];
    #pragma unroll
    for (int q=0;q<5;q++){ float4 v = wp[q]; wr[4*q]=v.x; wr[4*q+1]=v.y; wr[4*q+2]=v.z; wr[4*q+3]=v.w; }
    const float bc = dyn[oWEB+c];
    for (int k=lane;k<800;k+=32){
      const int l = k >> 4;
      const float4* rp = (const float4*)&xstage[l*20];
      float acc = bc;
      #pragma unroll
      for (int q=0;q<5;q++){
        float4 v = rp[q];
        acc = fmaf(v.x, wr[4*q], acc); acc = fmaf(v.y, wr[4*q+1], acc);
        acc = fmaf(v.z, wr[4*q+2], acc); acc = fmaf(v.w, wr[4*q+3], acc);
      }
      s.xe[k] = acc;
    }
  }
  __syncwarp();

  // ---- Phase B (f32x2 + MUFU tanh): attn[l][c], pairs of l ----
  {
    const int c  = lane & 15;
    const int ph = lane >> 4;
    u64 arp[16];
    #pragma unroll
    for (int cc=0;cc<16;cc++){ float v = dyn[oAW + c*17+cc]; arp[cc] = pk2(v,v); }
    const float ab = dyn[oAB+c];
    for (int p = ph; p < 25; p += 2){
      const int l = 2*p;
      u64 accA = pk2(ab, ab), accB = 0ull;
      #pragma unroll
      for (int cc=0;cc<8;cc++){
        accA = ffma2(arp[cc],   *(const u64*)&s.xe[cc*50+l],     accA);
        accB = ffma2(arp[cc+8], *(const u64*)&s.xe[(cc+8)*50+l], accB);
      }
      float2 v = up2(fadd2(accA, accB));
      s.attn[l*16+c]    = tanha(v.x);
      s.attn[l*16+16+c] = tanha(v.y);
    }
  }
  __syncwarp();

  // ---- Phase C: GRU with fused input pre-gates (MUFU nonlinearities) ----
  {
    const int g = lane < 18 ? lane : 0;
    float wr[16];
    {
      const float4* wp = (const float4*)&dyn[oWIH + g*20];
      #pragma unroll
      for (int q=0;q<4;q++){ float4 v=wp[q]; wr[4*q]=v.x; wr[4*q+1]=v.y; wr[4*q+2]=v.z; wr[4*q+3]=v.w; }
    }
    float wh[6];
    #pragma unroll
    for (int i=0;i<6;i++) wh[i]=dyn[oWHH + g*7+i];
    const float bg  = dyn[oBIH+g];
    const float bhg = dyn[oBHH+g];
    float h0=0,h1=0,h2=0,h3=0,h4=0,h5=0, hm=0;
    for (int l=0;l<50;l++){
      const float4* xp = (const float4*)&s.xe[l*16];
      float gi = bg;
      #pragma unroll
      for (int q=0;q<4;q++){
        float4 xv = xp[q];
        gi = fmaf(xv.x, wr[4*q], gi); gi = fmaf(xv.y, wr[4*q+1], gi);
        gi = fmaf(xv.z, wr[4*q+2], gi); gi = fmaf(xv.w, wr[4*q+3], gi);
      }
      float gh = bhg;
      gh = fmaf(wh[0],h0,gh); gh = fmaf(wh[1],h1,gh); gh = fmaf(wh[2],h2,gh);
      gh = fmaf(wh[3],h3,gh); gh = fmaf(wh[4],h4,gh); gh = fmaf(wh[5],h5,gh);
      const float a   = gi + gh;
      const float ar  = __shfl_sync(FULL, a,  lane);
      const float az  = __shfl_sync(FULL, a,  lane+6);
      const float gin = __shfl_sync(FULL, gi, lane+12);
      const float ghn = __shfl_sync(FULL, gh, lane+12);
      float hn = 0.f;
      if (lane < 6){
        const float r = sigma(ar);
        const float z = sigma(az);
        const float n = tanha(fmaf(r, ghn, gin));
        hn = (1.f - z)*n + z*hm;
        hm = hn;
        s.x4[l*6+lane] = hn;
      }
      h0=__shfl_sync(FULL,hn,0); h1=__shfl_sync(FULL,hn,1); h2=__shfl_sync(FULL,hn,2);
      h3=__shfl_sync(FULL,hn,3); h4=__shfl_sync(FULL,hn,4); h5=__shfl_sync(FULL,hn,5);
    }
  }
  __syncwarp();

  // ---- Phase E (l-split halves, c-loop unroll 4, no per-output shuffles) ----
  {
    const int j     = lane & 15;
    const int half  = lane >> 4;
    const int lbase = half*25;
    const float b1 = dyn[oC1B+j], b2 = dyn[oC2B+j], b3 = dyn[oC3B+j];
    float xc1 = 0.f, xc2 = 0.f, xc3 = 0.f;
    #pragma unroll
    for (int t5=0;t5<5;t5++){
      const int l0 = lbase + t5*5;   // half0: 0..20, half1: 25..45
      float acc1[5], acc2[5], acc3[5];
      #pragma unroll
      for (int lt=0;lt<5;lt++){ acc1[lt]=0.f; acc2[lt]=0.f; acc3[lt]=0.f; }
      #pragma unroll 4
      for (int c=0;c<16;c++){
        const float* xr = &s.xe[c*50];
        float win[9];               // t = l0-2 .. l0+6 (unconditional; memory-safe in dyn)
        #pragma unroll
        for (int off=0;off<9;off++) win[off] = xr[l0 + off - 2];
        if (t5==0 && half==0){ win[0]=0.f; win[1]=0.f; }      // t = -2, -1
        if (t5==4 && half==1){ win[7]=0.f; win[8]=0.f; }      // t = 50, 51
        const float wo  = dyn[oC1W + j*17 + c];
        const float w2a = dyn[oC2W + j*49 + c*3];
        const float w2b = dyn[oC2W + j*49 + c*3+1];
        const float w2c = dyn[oC2W + j*49 + c*3+2];
        const float w30 = dyn[oC3W + j*81 + c*5];
        const float w31 = dyn[oC3W + j*81 + c*5+1];
        const float w32 = dyn[oC3W + j*81 + c*5+2];
        const float w33 = dyn[oC3W + j*81 + c*5+3];
        const float w34 = dyn[oC3W + j*81 + c*5+4];
        #pragma unroll
        for (int lt=0;lt<5;lt++){
          acc1[lt] = fmaf(wo, win[lt+2], acc1[lt]);
          acc2[lt] = fmaf(w2a, win[lt+1], fmaf(w2b, win[lt+2], fmaf(w2c, win[lt+3], acc2[lt])));
          float a = acc3[lt];
          a = fmaf(w30, win[lt],   a);
          a = fmaf(w31, win[lt+1], a);
          a = fmaf(w32, win[lt+2], a);
          a = fmaf(w33, win[lt+3], a);
          a = fmaf(w34, win[lt+4], a);
          acc3[lt] = a;
        }
      }
      #pragma unroll
      for (int lt=0;lt<5;lt++){
        const int l = l0+lt;
        const float v1 = acc1[lt] + b1;
        const float v2 = acc2[lt] + b2;
        const float v3 = acc3[lt] + b3;
        const int i1 = j*50+l, i2 = (16+j)*50+l, i3 = (32+j)*50+l;
        xc1 = fmaf(lrelu(v1), s.attn[LUT[i1]], xc1);
        xc2 = fmaf(lrelu(v2), s.attn[LUT[i2]], xc2);
        xc3 = fmaf(lrelu(v3), s.attn[LUT[i3]], xc3);
      }
    }
    xc1 += __shfl_xor_sync(FULL, xc1, 16);
    xc2 += __shfl_xor_sync(FULL, xc2, 16);
    xc3 += __shfl_xor_sync(FULL, xc3, 16);
    if (half==0){ s.feat[j]=xc1; s.feat[16+j]=xc2; s.feat[32+j]=xc3; }
  }
  __syncwarp();

  // ---- Phase D (fused): score cache in xe region as half2, inv folded into PS ----
  {
    u32* eM = (u32*)s.xe;      // [25][53] u32; 1325 u32 < xe+attn (1600)
    if (lane < 25){
      float p2ja, p4ja, s6ja, p2jb, p4jb, s6jb;
      {
        const float2 a0=*(const float2*)&s.x4[lane*6], a1=*(const float2*)&s.x4[lane*6+2], a2=*(const float2*)&s.x4[lane*6+4];
        p2ja = a0.x+a0.y; p4ja = p2ja + a1.x+a1.y; s6ja = p4ja + a2.x+a2.y;
        const int jb6 = (lane+25)*6;
        const float2 b0=*(const float2*)&s.x4[jb6], b1=*(const float2*)&s.x4[jb6+2], b2=*(const float2*)&s.x4[jb6+4];
        p2jb = b0.x+b0.y; p4jb = p2jb + b1.x+b1.y; s6jb = p4jb + b2.x+b2.y;
      }
      const int ja = lane, jb = lane+25;
      float xra[6], xrb[6];
      #pragma unroll
      for (int h=0;h<6;h++){ xra[h]=s.x4[h*50+ja]; xrb[h]=s.x4[h*50+jb]; }
      float csa=0.f, csb=0.f;
      for (int i=0;i<50;i++){
        const float2 p0 = *(const float2*)&s.x4[i*6];
        const float2 p1 = *(const float2*)&s.x4[i*6+2];
        const float2 p2 = *(const float2*)&s.x4[i*6+4];
        float sa = p0.x*xra[0] + p0.y*xra[1];
        sa = fmaf(p1.x,xra[2], fmaf(p1.y,xra[3], sa));
        sa = fmaf(p2.x,xra[4], fmaf(p2.y,xra[5], sa));
        float sb = p0.x*xrb[0] + p0.y*xrb[1];
        sb = fmaf(p1.x,xrb[2], fmaf(p1.y,xrb[3], sb));
        sb = fmaf(p2.x,xrb[4], fmaf(p2.y,xrb[5], sb));
        const float ea = __expf(sa*(1.f/6.f));
        const float eb = __expf(sb*(1.f/6.f));
        csa += ea; csb += eb;
        __half2 hp = __floats2half2_rn(ea, eb);
        eM[lane*53+i] = *(u32*)&hp;
      }
      const float iva = __fdividef(1.f, csa);
      const float ivb = __fdividef(1.f, csb);
      s.p2a[ja] = p2ja*iva; s.p4a[ja] = p4ja*iva; s.s6a[ja] = s6ja*iva;
      s.p2a[jb] = p2jb*ivb; s.p4a[jb] = p4jb*ivb; s.s6a[jb] = s6jb*ivb;
    }
    __syncwarp();
    if (lane < 25){
      const int ia = lane, ib = lane+25;
      const int m = (ia*6) % 50;
      const float* PS = (m==48) ? s.p2a : (m==46) ? s.p4a : s.s6a;
      float la=0.f, ha=0.f, lb=0.f, hb=0.f;
      for (int j=0;j<25;j++){
        const u32 pa = eM[j*53+ia];
        const u32 pb = eM[j*53+ib];
        const float2 ea2 = __half22float2(*(const __half2*)&pa);
        const float2 eb2 = __half22float2(*(const __half2*)&pb);
        const float ps0 = PS[j],    hi0 = s.s6a[j]    - ps0;
        const float ps1 = PS[j+25], hi1 = s.s6a[j+25] - ps1;
        la = fmaf(ea2.x, ps0, la); ha = fmaf(ea2.x, hi0, ha);
        la = fmaf(ea2.y, ps1, la); ha = fmaf(ea2.y, hi1, ha);
        lb = fmaf(eb2.x, ps0, lb); hb = fmaf(eb2.x, hi0, hb);
        lb = fmaf(eb2.y, ps1, lb); hb = fmaf(eb2.y, hi1, hb);
      }
      *(float4*)&s.bred[lane*4] = make_float4(la, ha, lb, hb);
    }
    __syncwarp();
    if (lane < 6){
      float acc = 0.f;
      for (int L=0;L<25;L++){
        const int g0 = (L*6)/50;
        const float4 v = *(const float4*)&s.bred[L*4];
        if (g0==lane)   acc += v.x;
        if (g0==lane-1) acc += v.y;
        if (g0==lane-3) acc += v.z;
        if (g0==lane-4) acc += v.w;
      }
      s.feat[48+lane] = acc;
    }
  }
  __syncwarp();

  // ---- FC3 (parallel over lanes + shfl reduce) ----
  {
    float a0 = 0.f, a1 = 0.f;
    if (lane < 27){
      const float fa = s.feat[lane], fb = s.feat[lane+27];
      a0 = fa*dyn[oFC3+lane]    + fb*dyn[oFC3+lane+27];
      a1 = fa*dyn[oFC3+54+lane] + fb*dyn[oFC3+54+lane+27];
    }
    #pragma unroll
    for (int off=16; off>=1; off>>=1){
      a0 += __shfl_xor_sync(FULL, a0, off);
      a1 += __shfl_xor_sync(FULL, a1, off);
    }
    if (lane == 0){
      out[(size_t)b*2]   = a0 + dyn[oFC3B];
      out[(size_t)b*2+1] = a1 + dyn[oFC3B+1];
    }
  }
}

extern "C" void kernel_launch(void* const* d_in, const int* in_sizes, int n_in,
                              void* d_out, int out_size) {
  const float* x      = (const float*)d_in[0];
  const float* we_w   = (const float*)d_in[1];
  const float* we_b   = (const float*)d_in[2];
  const float* attn_w = (const float*)d_in[3];
  const float* attn_b = (const float*)d_in[4];
  const float* c1w    = (const float*)d_in[5];
  const float* c1b    = (const float*)d_in[6];
  const float* c2w    = (const float*)d_in[7];
  const float* c2b    = (const float*)d_in[8];
  const float* c3w    = (const float*)d_in[9];
  const float* c3b    = (const float*)d_in[10];
  const float* wih    = (const float*)d_in[11];
  const float* whh    = (const float*)d_in[12];
  const float* bih    = (const float*)d_in[13];
  const float* bhh    = (const float*)d_in[14];
  const float* fc3w   = (const float*)d_in[15];
  const float* fc3b   = (const float*)d_in[16];
  float* out = (float*)d_out;

  const int B = in_sizes[0] / 1000;
  const int blocks = (B + WPB - 1) / WPB;
  cudaFuncSetAttribute(nn_fused_kernel, cudaFuncAttributeMaxDynamicSharedMemorySize, SMEM_BYTES);
  nn_fused_kernel<<<blocks, WPB*32, SMEM_BYTES>>>(x, we_w, we_b, attn_w, attn_b,
                                  c1w, c1b, c2w, c2b, c3w, c3b,
                                  wih, whh, bih, bhh, fc3w, fc3b, out, B);
}

// round 15
// speedup vs baseline: 1.0947x; 1.0150x over previous
#include <cuda_runtime.h>
#include <cuda_fp16.h>

#define FULL 0xffffffffu
typedef unsigned long long u64;
typedef unsigned int u32;

__device__ __forceinline__ float lrelu(float v){ return v > 0.f ? v : 0.1f*v; }
__device__ __forceinline__ float tanha(float v){
  float r; asm("tanh.approx.f32 %0, %1;" : "=f"(r) : "f"(v)); return r;
}
__device__ __forceinline__ float sigma(float v){
  return fmaf(tanha(0.5f*v), 0.5f, 0.5f);
}
__device__ __forceinline__ u64 pk2(float lo, float hi){
  u64 r; asm("mov.b64 %0,{%1,%2};" : "=l"(r) : "f"(lo), "f"(hi)); return r;
}
__device__ __forceinline__ float2 up2(u64 v){
  float2 r; asm("mov.b64 {%0,%1},%2;" : "=f"(r.x), "=f"(r.y) : "l"(v)); return r;
}
__device__ __forceinline__ u64 ffma2(u64 a, u64 b, u64 c){
  u64 d; asm("fma.rn.f32x2 %0,%1,%2,%3;" : "=l"(d) : "l"(a), "l"(b), "l"(c)); return d;
}
__device__ __forceinline__ u64 fadd2(u64 a, u64 b){
  u64 d; asm("add.rn.f32x2 %0,%1,%2;" : "=l"(d) : "l"(a), "l"(b)); return d;
}

// ---- dynamic smem: weights region (+LUT) then WPB per-warp workspaces ----
#define oWEW   0      // 16 rows stride 20
#define oWEB   320
#define oAW    336    // 16 rows stride 17
#define oAB    608
#define oC1W   624    // 16 rows stride 17
#define oC1B   896
#define oC2W   912    // 16 rows stride 49, [j][c*3+k]
#define oC2B   1696
#define oC3W   1712   // 16 rows stride 81, [j][c*5+k]
#define oC3B   3008
#define oWIH   3024   // 18 rows stride 20
#define oBIH   3384
#define oWHH   3404   // 18 rows stride 7
#define oBHH   3530
#define oFC3   3552   // 108
#define oFC3B  3660
#define oLUT   3664   // u16[2400] = 1200 floats
#define W_TOT  4864   // 16B-aligned

struct WS {
  float xe[800];    // embed out, flat [l*16+c]; xr[c][l] view = xe[c*50+l]
  float attn[800];  // tanh attention [l][16]; ALSO x-staging; ALSO eM overflow in D
  float x4[304];    // GRU outputs flat [l*6+h]
  float p2a[52];    // per-j prefix sums over h (inv-scaled in D)
  float p4a[52];
  float s6a[52];
  float bred[104];  // per-lane (la,ha,lb,hb) bin partials
  float feat[56];
};                   // 2220 floats (8880 B, 16B multiple)

#define WPB 6
#define SMEM_FLOATS (W_TOT + WPB*2220)
#define SMEM_BYTES  (SMEM_FLOATS*4)

__global__ __launch_bounds__(WPB*32, 3) void nn_fused_kernel(
    const float* __restrict__ x,
    const float* __restrict__ we_w, const float* __restrict__ we_b,
    const float* __restrict__ attn_w, const float* __restrict__ attn_b,
    const float* __restrict__ c1w, const float* __restrict__ c1b,
    const float* __restrict__ c2w, const float* __restrict__ c2b,
    const float* __restrict__ c3w, const float* __restrict__ c3b,
    const float* __restrict__ wih, const float* __restrict__ whh,
    const float* __restrict__ bih, const float* __restrict__ bhh,
    const float* __restrict__ fc3w, const float* __restrict__ fc3b,
    float* __restrict__ out, int B)
{
  extern __shared__ float dyn[];
  const int tid = threadIdx.x;
  const int NT = WPB*32;

  // ---- cooperative weight load ----
  for (int i=tid;i<320;i+=NT)  dyn[oWEW + i] = we_w[i];
  for (int i=tid;i<256;i+=NT)  dyn[oAW  + (i>>4)*17+(i&15)] = attn_w[i];
  for (int i=tid;i<256;i+=NT)  dyn[oC1W + (i>>4)*17+(i&15)] = c1w[i];
  for (int i=tid;i<768;i+=NT)  dyn[oC2W + (i/48)*49+(i%48)] = c2w[i];
  for (int i=tid;i<1280;i+=NT) dyn[oC3W + (i/80)*81+(i%80)] = c3w[i];
  for (int i=tid;i<288;i+=NT)  dyn[oWIH + (i>>4)*20+(i&15)] = wih[i];
  for (int i=tid;i<108;i+=NT)  dyn[oWHH + (i/6)*7+(i%6)]    = whh[i];
  for (int i=tid;i<108;i+=NT)  dyn[oFC3 + i] = fc3w[i];
  {
    unsigned short* LUT = (unsigned short*)(dyn + oLUT);
    for (int i=tid;i<2400;i+=NT) LUT[i] = (unsigned short)((i/48)*16 + (i&15));
  }
  if (tid<16){ dyn[oWEB+tid]=we_b[tid]; dyn[oAB+tid]=attn_b[tid];
               dyn[oC1B+tid]=c1b[tid]; dyn[oC2B+tid]=c2b[tid]; dyn[oC3B+tid]=c3b[tid]; }
  if (tid>=32 && tid<50){ dyn[oBIH+tid-32]=bih[tid-32]; dyn[oBHH+tid-32]=bhh[tid-32]; }
  if (tid==50){ dyn[oFC3B]=fc3b[0]; dyn[oFC3B+1]=fc3b[1]; }
  __syncthreads();

  const int w    = tid >> 5;
  const int lane = tid & 31;
  WS& s = *((WS*)(dyn + W_TOT) + w);
  const unsigned short* LUT = (const unsigned short*)(dyn + oLUT);
  const int b = blockIdx.x*WPB + w;
  if (b >= B) return;

  // ---- stage x [50][20] into attn..x4 region via float4 ----
  float* xstage = s.attn;
  {
    const float4* xb4 = (const float4*)(x + (size_t)b*1000);
    float4* r4 = (float4*)xstage;
    for (int i=lane;i<250;i+=32) r4[i] = xb4[i];
  }
  __syncwarp();

  // ---- Phase A: xe[l][c] = x[l,:] . we_w[c,:] + b[c] ----
  {
    const int c = lane & 15;
    float wr[20];
    const float4* wp = (const float4*)&dyn[oWEW + c*20];
    #pragma unroll
    for (int q=0;q<5;q++){ float4 v = wp[q]; wr[4*q]=v.x; wr[4*q+1]=v.y; wr[4*q+2]=v.z; wr[4*q+3]=v.w; }
    const float bc = dyn[oWEB+c];
    for (int k=lane;k<800;k+=32){
      const int l = k >> 4;
      const float4* rp = (const float4*)&xstage[l*20];
      float acc = bc;
      #pragma unroll
      for (int q=0;q<5;q++){
        float4 v = rp[q];
        acc = fmaf(v.x, wr[4*q], acc); acc = fmaf(v.y, wr[4*q+1], acc);
        acc = fmaf(v.z, wr[4*q+2], acc); acc = fmaf(v.w, wr[4*q+3], acc);
      }
      s.xe[k] = acc;
    }
  }
  __syncwarp();

  // ---- Phase B (f32x2 + MUFU tanh): attn[l][c], pairs of l ----
  {
    const int c  = lane & 15;
    const int ph = lane >> 4;
    u64 arp[16];
    #pragma unroll
    for (int cc=0;cc<16;cc++){ float v = dyn[oAW + c*17+cc]; arp[cc] = pk2(v,v); }
    const float ab = dyn[oAB+c];
    for (int p = ph; p < 25; p += 2){
      const int l = 2*p;
      u64 accA = pk2(ab, ab), accB = 0ull;
      #pragma unroll
      for (int cc=0;cc<8;cc++){
        accA = ffma2(arp[cc],   *(const u64*)&s.xe[cc*50+l],     accA);
        accB = ffma2(arp[cc+8], *(const u64*)&s.xe[(cc+8)*50+l], accB);
      }
      float2 v = up2(fadd2(accA, accB));
      s.attn[l*16+c]    = tanha(v.x);
      s.attn[l*16+16+c] = tanha(v.y);
    }
  }
  __syncwarp();

  // ---- Phase C: GRU with fused input pre-gates (MUFU nonlinearities) ----
  {
    const int g = lane < 18 ? lane : 0;
    float wr[16];
    {
      const float4* wp = (const float4*)&dyn[oWIH + g*20];
      #pragma unroll
      for (int q=0;q<4;q++){ float4 v=wp[q]; wr[4*q]=v.x; wr[4*q+1]=v.y; wr[4*q+2]=v.z; wr[4*q+3]=v.w; }
    }
    float wh[6];
    #pragma unroll
    for (int i=0;i<6;i++) wh[i]=dyn[oWHH + g*7+i];
    const float bg  = dyn[oBIH+g];
    const float bhg = dyn[oBHH+g];
    float h0=0,h1=0,h2=0,h3=0,h4=0,h5=0, hm=0;
    for (int l=0;l<50;l++){
      const float4* xp = (const float4*)&s.xe[l*16];
      float gi = bg;
      #pragma unroll
      for (int q=0;q<4;q++){
        float4 xv = xp[q];
        gi = fmaf(xv.x, wr[4*q], gi); gi = fmaf(xv.y, wr[4*q+1], gi);
        gi = fmaf(xv.z, wr[4*q+2], gi); gi = fmaf(xv.w, wr[4*q+3], gi);
      }
      float gh = bhg;
      gh = fmaf(wh[0],h0,gh); gh = fmaf(wh[1],h1,gh); gh = fmaf(wh[2],h2,gh);
      gh = fmaf(wh[3],h3,gh); gh = fmaf(wh[4],h4,gh); gh = fmaf(wh[5],h5,gh);
      const float a   = gi + gh;
      const float ar  = __shfl_sync(FULL, a,  lane);
      const float az  = __shfl_sync(FULL, a,  lane+6);
      const float gin = __shfl_sync(FULL, gi, lane+12);
      const float ghn = __shfl_sync(FULL, gh, lane+12);
      float hn = 0.f;
      if (lane < 6){
        const float r = sigma(ar);
        const float z = sigma(az);
        const float n = tanha(fmaf(r, ghn, gin));
        hn = (1.f - z)*n + z*hm;
        hm = hn;
        s.x4[l*6+lane] = hn;
      }
      h0=__shfl_sync(FULL,hn,0); h1=__shfl_sync(FULL,hn,1); h2=__shfl_sync(FULL,hn,2);
      h3=__shfl_sync(FULL,hn,3); h4=__shfl_sync(FULL,hn,4); h5=__shfl_sync(FULL,hn,5);
    }
  }
  __syncwarp();

  // ---- Phase E (l-split halves, c-loop unroll 4, no per-output shuffles) ----
  {
    const int j     = lane & 15;
    const int half  = lane >> 4;
    const int lbase = half*25;
    const float b1 = dyn[oC1B+j], b2 = dyn[oC2B+j], b3 = dyn[oC3B+j];
    float xc1 = 0.f, xc2 = 0.f, xc3 = 0.f;
    #pragma unroll
    for (int t5=0;t5<5;t5++){
      const int l0 = lbase + t5*5;   // half0: 0..20, half1: 25..45
      float acc1[5], acc2[5], acc3[5];
      #pragma unroll
      for (int lt=0;lt<5;lt++){ acc1[lt]=0.f; acc2[lt]=0.f; acc3[lt]=0.f; }
      #pragma unroll 4
      for (int c=0;c<16;c++){
        const float* xr = &s.xe[c*50];
        float win[9];               // t = l0-2 .. l0+6 (unconditional; memory-safe in dyn)
        #pragma unroll
        for (int off=0;off<9;off++) win[off] = xr[l0 + off - 2];
        if (t5==0 && half==0){ win[0]=0.f; win[1]=0.f; }      // t = -2, -1
        if (t5==4 && half==1){ win[7]=0.f; win[8]=0.f; }      // t = 50, 51
        const float wo  = dyn[oC1W + j*17 + c];
        const float w2a = dyn[oC2W + j*49 + c*3];
        const float w2b = dyn[oC2W + j*49 + c*3+1];
        const float w2c = dyn[oC2W + j*49 + c*3+2];
        const float w30 = dyn[oC3W + j*81 + c*5];
        const float w31 = dyn[oC3W + j*81 + c*5+1];
        const float w32 = dyn[oC3W + j*81 + c*5+2];
        const float w33 = dyn[oC3W + j*81 + c*5+3];
        const float w34 = dyn[oC3W + j*81 + c*5+4];
        #pragma unroll
        for (int lt=0;lt<5;lt++){
          acc1[lt] = fmaf(wo, win[lt+2], acc1[lt]);
          acc2[lt] = fmaf(w2a, win[lt+1], fmaf(w2b, win[lt+2], fmaf(w2c, win[lt+3], acc2[lt])));
          float a = acc3[lt];
          a = fmaf(w30, win[lt],   a);
          a = fmaf(w31, win[lt+1], a);
          a = fmaf(w32, win[lt+2], a);
          a = fmaf(w33, win[lt+3], a);
          a = fmaf(w34, win[lt+4], a);
          acc3[lt] = a;
        }
      }
      #pragma unroll
      for (int lt=0;lt<5;lt++){
        const int l = l0+lt;
        const float v1 = acc1[lt] + b1;
        const float v2 = acc2[lt] + b2;
        const float v3 = acc3[lt] + b3;
        const int i1 = j*50+l, i2 = (16+j)*50+l, i3 = (32+j)*50+l;
        xc1 = fmaf(lrelu(v1), s.attn[LUT[i1]], xc1);
        xc2 = fmaf(lrelu(v2), s.attn[LUT[i2]], xc2);
        xc3 = fmaf(lrelu(v3), s.attn[LUT[i3]], xc3);
      }
    }
    xc1 += __shfl_xor_sync(FULL, xc1, 16);
    xc2 += __shfl_xor_sync(FULL, xc2, 16);
    xc3 += __shfl_xor_sync(FULL, xc3, 16);
    if (half==0){ s.feat[j]=xc1; s.feat[16+j]=xc2; s.feat[32+j]=xc3; }
  }
  __syncwarp();

  // ---- Phase D (fused): score cache in xe region as half2, inv folded into PS ----
  {
    u32* eM = (u32*)s.xe;      // [25][53] u32; 1325 u32 < xe+attn (1600)
    if (lane < 25){
      float p2ja, p4ja, s6ja, p2jb, p4jb, s6jb;
      {
        const float2 a0=*(const float2*)&s.x4[lane*6], a1=*(const float2*)&s.x4[lane*6+2], a2=*(const float2*)&s.x4[lane*6+4];
        p2ja = a0.x+a0.y; p4ja = p2ja + a1.x+a1.y; s6ja = p4ja + a2.x+a2.y;
        const int jb6 = (lane+25)*6;
        const float2 b0=*(const float2*)&s.x4[jb6], b1=*(const float2*)&s.x4[jb6+2], b2=*(const float2*)&s.x4[jb6+4];
        p2jb = b0.x+b0.y; p4jb = p2jb + b1.x+b1.y; s6jb = p4jb + b2.x+b2.y;
      }
      const int ja = lane, jb = lane+25;
      float xra[6], xrb[6];
      #pragma unroll
      for (int h=0;h<6;h++){ xra[h]=s.x4[h*50+ja]; xrb[h]=s.x4[h*50+jb]; }
      float csa=0.f, csb=0.f;
      for (int i=0;i<50;i++){
        const float2 p0 = *(const float2*)&s.x4[i*6];
        const float2 p1 = *(const float2*)&s.x4[i*6+2];
        const float2 p2 = *(const float2*)&s.x4[i*6+4];
        float sa = p0.x*xra[0] + p0.y*xra[1];
        sa = fmaf(p1.x,xra[2], fmaf(p1.y,xra[3], sa));
        sa = fmaf(p2.x,xra[4], fmaf(p2.y,xra[5], sa));
        float sb = p0.x*xrb[0] + p0.y*xrb[1];
        sb = fmaf(p1.x,xrb[2], fmaf(p1.y,xrb[3], sb));
        sb = fmaf(p2.x,xrb[4], fmaf(p2.y,xrb[5], sb));
        const float ea = __expf(sa*(1.f/6.f));
        const float eb = __expf(sb*(1.f/6.f));
        csa += ea; csb += eb;
        __half2 hp = __floats2half2_rn(ea, eb);
        eM[lane*53+i] = *(u32*)&hp;
      }
      const float iva = __fdividef(1.f, csa);
      const float ivb = __fdividef(1.f, csb);
      s.p2a[ja] = p2ja*iva; s.p4a[ja] = p4ja*iva; s.s6a[ja] = s6ja*iva;
      s.p2a[jb] = p2jb*ivb; s.p4a[jb] = p4jb*ivb; s.s6a[jb] = s6jb*ivb;
    }
    __syncwarp();
    if (lane < 25){
      const int ia = lane, ib = lane+25;
      const int m = (ia*6) % 50;
      const float* PS = (m==48) ? s.p2a : (m==46) ? s.p4a : s.s6a;
      float la=0.f, ha=0.f, lb=0.f, hb=0.f;
      for (int j=0;j<25;j++){
        const u32 pa = eM[j*53+ia];
        const u32 pb = eM[j*53+ib];
        const float2 ea2 = __half22float2(*(const __half2*)&pa);
        const float2 eb2 = __half22float2(*(const __half2*)&pb);
        const float ps0 = PS[j],    hi0 = s.s6a[j]    - ps0;
        const float ps1 = PS[j+25], hi1 = s.s6a[j+25] - ps1;
        la = fmaf(ea2.x, ps0, la); ha = fmaf(ea2.x, hi0, ha);
        la = fmaf(ea2.y, ps1, la); ha = fmaf(ea2.y, hi1, ha);
        lb = fmaf(eb2.x, ps0, lb); hb = fmaf(eb2.x, hi0, hb);
        lb = fmaf(eb2.y, ps1, lb); hb = fmaf(eb2.y, hi1, hb);
      }
      *(float4*)&s.bred[lane*4] = make_float4(la, ha, lb, hb);
    }
    __syncwarp();
    if (lane < 6){
      float acc = 0.f;
      for (int L=0;L<25;L++){
        const int g0 = (L*6)/50;
        const float4 v = *(const float4*)&s.bred[L*4];
        if (g0==lane)   acc += v.x;
        if (g0==lane-1) acc += v.y;
        if (g0==lane-3) acc += v.z;
        if (g0==lane-4) acc += v.w;
      }
      s.feat[48+lane] = acc;
    }
  }
  __syncwarp();

  // ---- FC3 (parallel over lanes + shfl reduce) ----
  {
    float a0 = 0.f, a1 = 0.f;
    if (lane < 27){
      const float fa = s.feat[lane], fb = s.feat[lane+27];
      a0 = fa*dyn[oFC3+lane]    + fb*dyn[oFC3+lane+27];
      a1 = fa*dyn[oFC3+54+lane] + fb*dyn[oFC3+54+lane+27];
    }
    #pragma unroll
    for (int off=16; off>=1; off>>=1){
      a0 += __shfl_xor_sync(FULL, a0, off);
      a1 += __shfl_xor_sync(FULL, a1, off);
    }
    if (lane == 0){
      out[(size_t)b*2]   = a0 + dyn[oFC3B];
      out[(size_t)b*2+1] = a1 + dyn[oFC3B+1];
    }
  }
}

extern "C" void kernel_launch(void* const* d_in, const int* in_sizes, int n_in,
                              void* d_out, int out_size) {
  const float* x      = (const float*)d_in[0];
  const float* we_w   = (const float*)d_in[1];
  const float* we_b   = (const float*)d_in[2];
  const float* attn_w = (const float*)d_in[3];
  const float* attn_b = (const float*)d_in[4];
  const float* c1w    = (const float*)d_in[5];
  const float* c1b    = (const float*)d_in[6];
  const float* c2w    = (const float*)d_in[7];
  const float* c2b    = (const float*)d_in[8];
  const float* c3w    = (const float*)d_in[9];
  const float* c3b    = (const float*)d_in[10];
  const float* wih    = (const float*)d_in[11];
  const float* whh    = (const float*)d_in[12];
  const float* bih    = (const float*)d_in[13];
  const float* bhh    = (const float*)d_in[14];
  const float* fc3w   = (const float*)d_in[15];
  const float* fc3b   = (const float*)d_in[16];
  float* out = (float*)d_out;

  const int B = in_sizes[0] / 1000;
  const int blocks = (B + WPB - 1) / WPB;
  cudaFuncSetAttribute(nn_fused_kernel, cudaFuncAttributeMaxDynamicSharedMemorySize, SMEM_BYTES);
  nn_fused_kernel<<<blocks, WPB*32, SMEM_BYTES>>>(x, we_w, we_b, attn_w, attn_b,
                                  c1w, c1b, c2w, c2b, c3w, c3b,
                                  wih, whh, bih, bhh, fc3w, fc3b, out, B);
}

// round 16
// speedup vs baseline: 1.1136x; 1.0172x over previous
#include <cuda_runtime.h>
#include <cuda_fp16.h>

#define FULL 0xffffffffu
typedef unsigned long long u64;
typedef unsigned int u32;

__device__ __forceinline__ float lrelu(float v){ return v > 0.f ? v : 0.1f*v; }
__device__ __forceinline__ float tanha(float v){
  float r; asm("tanh.approx.f32 %0, %1;" : "=f"(r) : "f"(v)); return r;
}
__device__ __forceinline__ float sigma(float v){
  return fmaf(tanha(0.5f*v), 0.5f, 0.5f);
}
__device__ __forceinline__ u64 pk2(float lo, float hi){
  u64 r; asm("mov.b64 %0,{%1,%2};" : "=l"(r) : "f"(lo), "f"(hi)); return r;
}
__device__ __forceinline__ float2 up2(u64 v){
  float2 r; asm("mov.b64 {%0,%1},%2;" : "=f"(r.x), "=f"(r.y) : "l"(v)); return r;
}
__device__ __forceinline__ u64 ffma2(u64 a, u64 b, u64 c){
  u64 d; asm("fma.rn.f32x2 %0,%1,%2,%3;" : "=l"(d) : "l"(a), "l"(b), "l"(c)); return d;
}
__device__ __forceinline__ u64 fadd2(u64 a, u64 b){
  u64 d; asm("add.rn.f32x2 %0,%1,%2;" : "=l"(d) : "l"(a), "l"(b)); return d;
}

// ---- dynamic smem: weights region (+LUT) then WPB per-warp workspaces ----
#define oWEW   0      // 16 rows stride 20
#define oWEB   320
#define oAW    336    // 16 rows stride 17
#define oAB    608
#define oC1W   624    // 16 rows stride 17
#define oC1B   896
#define oC2W   912    // 16 rows stride 49, [j][c*3+k]
#define oC2B   1696
#define oC3W   1712   // 16 rows stride 81, [j][c*5+k]
#define oC3B   3008
#define oWIH   3024   // 18 rows stride 20
#define oBIH   3384
#define oWHH   3404   // 18 rows stride 7
#define oBHH   3530
#define oFC3   3552   // 108
#define oFC3B  3660
#define oLUT   3664   // u16[2400] = 1200 floats
#define W_TOT  4864   // 16B-aligned

struct WS {
  float xe[800];    // embed out, flat [l*16+c]; xr[c][l] view = xe[c*50+l]
  float attn[800];  // tanh attention [l][16]; ALSO x-staging; ALSO eM overflow in D
  float x4[304];    // GRU outputs flat [l*6+h]
  float p2a[52];    // per-j prefix sums over h (inv-scaled in D)
  float p4a[52];
  float s6a[52];
  float bred[104];  // per-lane (la,ha,lb,hb) bin partials
  float feat[56];
};                   // 2220 floats

#define WPB 6
#define SMEM_FLOATS (W_TOT + WPB*2220)
#define SMEM_BYTES  (SMEM_FLOATS*4)

__global__ __launch_bounds__(WPB*32, 3) void nn_fused_kernel(
    const float* __restrict__ x,
    const float* __restrict__ we_w, const float* __restrict__ we_b,
    const float* __restrict__ attn_w, const float* __restrict__ attn_b,
    const float* __restrict__ c1w, const float* __restrict__ c1b,
    const float* __restrict__ c2w, const float* __restrict__ c2b,
    const float* __restrict__ c3w, const float* __restrict__ c3b,
    const float* __restrict__ wih, const float* __restrict__ whh,
    const float* __restrict__ bih, const float* __restrict__ bhh,
    const float* __restrict__ fc3w, const float* __restrict__ fc3b,
    float* __restrict__ out, int B)
{
  extern __shared__ float dyn[];
  const int tid = threadIdx.x;
  const int NT = WPB*32;

  // ---- cooperative weight load ----
  for (int i=tid;i<320;i+=NT)  dyn[oWEW + i] = we_w[i];
  for (int i=tid;i<256;i+=NT)  dyn[oAW  + (i>>4)*17+(i&15)] = attn_w[i];
  for (int i=tid;i<256;i+=NT)  dyn[oC1W + (i>>4)*17+(i&15)] = c1w[i];
  for (int i=tid;i<768;i+=NT)  dyn[oC2W + (i/48)*49+(i%48)] = c2w[i];
  for (int i=tid;i<1280;i+=NT) dyn[oC3W + (i/80)*81+(i%80)] = c3w[i];
  for (int i=tid;i<288;i+=NT)  dyn[oWIH + (i>>4)*20+(i&15)] = wih[i];
  for (int i=tid;i<108;i+=NT)  dyn[oWHH + (i/6)*7+(i%6)]    = whh[i];
  for (int i=tid;i<108;i+=NT)  dyn[oFC3 + i] = fc3w[i];
  {
    unsigned short* LUT = (unsigned short*)(dyn + oLUT);
    for (int i=tid;i<2400;i+=NT) LUT[i] = (unsigned short)((i/48)*16 + (i&15));
  }
  if (tid<16){ dyn[oWEB+tid]=we_b[tid]; dyn[oAB+tid]=attn_b[tid];
               dyn[oC1B+tid]=c1b[tid]; dyn[oC2B+tid]=c2b[tid]; dyn[oC3B+tid]=c3b[tid]; }
  if (tid>=32 && tid<50){ dyn[oBIH+tid-32]=bih[tid-32]; dyn[oBHH+tid-32]=bhh[tid-32]; }
  if (tid==50){ dyn[oFC3B]=fc3b[0]; dyn[oFC3B+1]=fc3b[1]; }
  __syncthreads();

  const int w    = tid >> 5;
  const int lane = tid & 31;
  WS& s = *((WS*)(dyn + W_TOT) + w);
  const unsigned short* LUT = (const unsigned short*)(dyn + oLUT);
  const int b = blockIdx.x*WPB + w;
  if (b >= B) return;

  // ---- stage x [50][20] into attn..x4 region via float4 ----
  float* xstage = s.attn;
  {
    const float4* xb4 = (const float4*)(x + (size_t)b*1000);
    float4* r4 = (float4*)xstage;
    for (int i=lane;i<250;i+=32) r4[i] = xb4[i];
  }
  __syncwarp();

  // ---- Phase A: xe[l][c] = x[l,:] . we_w[c,:] + b[c] ----
  {
    const int c = lane & 15;
    float wr[20];
    const float4* wp = (const float4*)&dyn[oWEW + c*20];
    #pragma unroll
    for (int q=0;q<5;q++){ float4 v = wp[q]; wr[4*q]=v.x; wr[4*q+1]=v.y; wr[4*q+2]=v.z; wr[4*q+3]=v.w; }
    const float bc = dyn[oWEB+c];
    for (int k=lane;k<800;k+=32){
      const int l = k >> 4;
      const float4* rp = (const float4*)&xstage[l*20];
      float acc = bc;
      #pragma unroll
      for (int q=0;q<5;q++){
        float4 v = rp[q];
        acc = fmaf(v.x, wr[4*q], acc); acc = fmaf(v.y, wr[4*q+1], acc);
        acc = fmaf(v.z, wr[4*q+2], acc); acc = fmaf(v.w, wr[4*q+3], acc);
      }
      s.xe[k] = acc;
    }
  }
  __syncwarp();

  // ---- Phase B (f32x2 + MUFU tanh): attn[l][c], pairs of l ----
  {
    const int c  = lane & 15;
    const int ph = lane >> 4;
    u64 arp[16];
    #pragma unroll
    for (int cc=0;cc<16;cc++){ float v = dyn[oAW + c*17+cc]; arp[cc] = pk2(v,v); }
    const float ab = dyn[oAB+c];
    for (int p = ph; p < 25; p += 2){
      const int l = 2*p;
      u64 accA = pk2(ab, ab), accB = 0ull;
      #pragma unroll
      for (int cc=0;cc<8;cc++){
        accA = ffma2(arp[cc],   *(const u64*)&s.xe[cc*50+l],     accA);
        accB = ffma2(arp[cc+8], *(const u64*)&s.xe[(cc+8)*50+l], accB);
      }
      float2 v = up2(fadd2(accA, accB));
      s.attn[l*16+c]    = tanha(v.x);
      s.attn[l*16+16+c] = tanha(v.y);
    }
  }
  __syncwarp();

  // ---- Phase C: GRU with fused input pre-gates (MUFU nonlinearities) ----
  {
    const int g = lane < 18 ? lane : 0;
    float wr[16];
    {
      const float4* wp = (const float4*)&dyn[oWIH + g*20];
      #pragma unroll
      for (int q=0;q<4;q++){ float4 v=wp[q]; wr[4*q]=v.x; wr[4*q+1]=v.y; wr[4*q+2]=v.z; wr[4*q+3]=v.w; }
    }
    float wh[6];
    #pragma unroll
    for (int i=0;i<6;i++) wh[i]=dyn[oWHH + g*7+i];
    const float bg  = dyn[oBIH+g];
    const float bhg = dyn[oBHH+g];
    float h0=0,h1=0,h2=0,h3=0,h4=0,h5=0, hm=0;
    for (int l=0;l<50;l++){
      const float4* xp = (const float4*)&s.xe[l*16];
      float gi = bg;
      #pragma unroll
      for (int q=0;q<4;q++){
        float4 xv = xp[q];
        gi = fmaf(xv.x, wr[4*q], gi); gi = fmaf(xv.y, wr[4*q+1], gi);
        gi = fmaf(xv.z, wr[4*q+2], gi); gi = fmaf(xv.w, wr[4*q+3], gi);
      }
      float gh = bhg;
      gh = fmaf(wh[0],h0,gh); gh = fmaf(wh[1],h1,gh); gh = fmaf(wh[2],h2,gh);
      gh = fmaf(wh[3],h3,gh); gh = fmaf(wh[4],h4,gh); gh = fmaf(wh[5],h5,gh);
      const float a   = gi + gh;
      const float ar  = __shfl_sync(FULL, a,  lane);
      const float az  = __shfl_sync(FULL, a,  lane+6);
      const float gin = __shfl_sync(FULL, gi, lane+12);
      const float ghn = __shfl_sync(FULL, gh, lane+12);
      float hn = 0.f;
      if (lane < 6){
        const float r = sigma(ar);
        const float z = sigma(az);
        const float n = tanha(fmaf(r, ghn, gin));
        hn = (1.f - z)*n + z*hm;
        hm = hn;
        s.x4[l*6+lane] = hn;
      }
      h0=__shfl_sync(FULL,hn,0); h1=__shfl_sync(FULL,hn,1); h2=__shfl_sync(FULL,hn,2);
      h3=__shfl_sync(FULL,hn,3); h4=__shfl_sync(FULL,hn,4); h5=__shfl_sync(FULL,hn,5);
    }
  }
  __syncwarp();

  // ---- Phase E (l-split halves, 2-pass, weights hoisted per (pass,c)) ----
  {
    const int j     = lane & 15;
    const int half  = lane >> 4;
    const int lbase = half*25;
    const float b1 = dyn[oC1B+j], b2 = dyn[oC2B+j], b3 = dyn[oC3B+j];
    float xc1 = 0.f, xc2 = 0.f, xc3 = 0.f;
    #pragma unroll
    for (int P=0;P<2;P++){
      const int o0 = lbase + (P ? 13 : 0);   // pass0: 13 outputs, pass1: 12
      const int NO = P ? 12 : 13;
      float acc1[13], acc2[13], acc3[13];
      #pragma unroll
      for (int o=0;o<13;o++){ acc1[o]=0.f; acc2[o]=0.f; acc3[o]=0.f; }
      #pragma unroll 2
      for (int c=0;c<16;c++){
        const float* xr = &s.xe[c*50];
        float win[17];              // taps t = o0-2 .. o0+14 (unconditional; memory-safe)
        #pragma unroll
        for (int off=0;off<17;off++) win[off] = xr[o0 + off - 2];
        if (P==0 && half==0){ win[0]=0.f; win[1]=0.f; }              // t = -2, -1
        if (P==1 && half==1){ win[14]=0.f; win[15]=0.f; win[16]=0.f; } // t = 50, 51, 52
        const float wo  = dyn[oC1W + j*17 + c];
        const float w2a = dyn[oC2W + j*49 + c*3];
        const float w2b = dyn[oC2W + j*49 + c*3+1];
        const float w2c = dyn[oC2W + j*49 + c*3+2];
        const float w30 = dyn[oC3W + j*81 + c*5];
        const float w31 = dyn[oC3W + j*81 + c*5+1];
        const float w32 = dyn[oC3W + j*81 + c*5+2];
        const float w33 = dyn[oC3W + j*81 + c*5+3];
        const float w34 = dyn[oC3W + j*81 + c*5+4];
        #pragma unroll
        for (int o=0;o<13;o++){
          if (o >= NO) break;
          acc1[o] = fmaf(wo, win[o+2], acc1[o]);
          acc2[o] = fmaf(w2a, win[o+1], fmaf(w2b, win[o+2], fmaf(w2c, win[o+3], acc2[o])));
          float a = acc3[o];
          a = fmaf(w30, win[o],   a);
          a = fmaf(w31, win[o+1], a);
          a = fmaf(w32, win[o+2], a);
          a = fmaf(w33, win[o+3], a);
          a = fmaf(w34, win[o+4], a);
          acc3[o] = a;
        }
      }
      #pragma unroll
      for (int o=0;o<13;o++){
        if (o >= NO) break;
        const int l = o0 + o;
        const float v1 = acc1[o] + b1;
        const float v2 = acc2[o] + b2;
        const float v3 = acc3[o] + b3;
        const int i1 = j*50+l, i2 = (16+j)*50+l, i3 = (32+j)*50+l;
        xc1 = fmaf(lrelu(v1), s.attn[LUT[i1]], xc1);
        xc2 = fmaf(lrelu(v2), s.attn[LUT[i2]], xc2);
        xc3 = fmaf(lrelu(v3), s.attn[LUT[i3]], xc3);
      }
    }
    xc1 += __shfl_xor_sync(FULL, xc1, 16);
    xc2 += __shfl_xor_sync(FULL, xc2, 16);
    xc3 += __shfl_xor_sync(FULL, xc3, 16);
    if (half==0){ s.feat[j]=xc1; s.feat[16+j]=xc2; s.feat[32+j]=xc3; }
  }
  __syncwarp();

  // ---- Phase D (fused): score cache in xe region as half2, inv folded into PS ----
  {
    u32* eM = (u32*)s.xe;      // [25][53] u32; 1325 u32 < xe+attn (1600)
    if (lane < 25){
      float p2ja, p4ja, s6ja, p2jb, p4jb, s6jb;
      {
        const float2 a0=*(const float2*)&s.x4[lane*6], a1=*(const float2*)&s.x4[lane*6+2], a2=*(const float2*)&s.x4[lane*6+4];
        p2ja = a0.x+a0.y; p4ja = p2ja + a1.x+a1.y; s6ja = p4ja + a2.x+a2.y;
        const int jb6 = (lane+25)*6;
        const float2 b0=*(const float2*)&s.x4[jb6], b1=*(const float2*)&s.x4[jb6+2], b2=*(const float2*)&s.x4[jb6+4];
        p2jb = b0.x+b0.y; p4jb = p2jb + b1.x+b1.y; s6jb = p4jb + b2.x+b2.y;
      }
      const int ja = lane, jb = lane+25;
      float xra[6], xrb[6];
      #pragma unroll
      for (int h=0;h<6;h++){ xra[h]=s.x4[h*50+ja]; xrb[h]=s.x4[h*50+jb]; }
      float csa=0.f, csb=0.f;
      for (int i=0;i<50;i++){
        const float2 p0 = *(const float2*)&s.x4[i*6];
        const float2 p1 = *(const float2*)&s.x4[i*6+2];
        const float2 p2 = *(const float2*)&s.x4[i*6+4];
        float sa = p0.x*xra[0] + p0.y*xra[1];
        sa = fmaf(p1.x,xra[2], fmaf(p1.y,xra[3], sa));
        sa = fmaf(p2.x,xra[4], fmaf(p2.y,xra[5], sa));
        float sb = p0.x*xrb[0] + p0.y*xrb[1];
        sb = fmaf(p1.x,xrb[2], fmaf(p1.y,xrb[3], sb));
        sb = fmaf(p2.x,xrb[4], fmaf(p2.y,xrb[5], sb));
        const float ea = __expf(sa*(1.f/6.f));
        const float eb = __expf(sb*(1.f/6.f));
        csa += ea; csb += eb;
        __half2 hp = __floats2half2_rn(ea, eb);
        eM[lane*53+i] = *(u32*)&hp;
      }
      const float iva = __fdividef(1.f, csa);
      const float ivb = __fdividef(1.f, csb);
      s.p2a[ja] = p2ja*iva; s.p4a[ja] = p4ja*iva; s.s6a[ja] = s6ja*iva;
      s.p2a[jb] = p2jb*ivb; s.p4a[jb] = p4jb*ivb; s.s6a[jb] = s6jb*ivb;
    }
    __syncwarp();
    if (lane < 25){
      const int ia = lane, ib = lane+25;
      const int m = (ia*6) % 50;
      const float* PS = (m==48) ? s.p2a : (m==46) ? s.p4a : s.s6a;
      float la=0.f, ha=0.f, lb=0.f, hb=0.f;
      for (int j=0;j<25;j++){
        const u32 pa = eM[j*53+ia];
        const u32 pb = eM[j*53+ib];
        const float2 ea2 = __half22float2(*(const __half2*)&pa);
        const float2 eb2 = __half22float2(*(const __half2*)&pb);
        const float ps0 = PS[j],    hi0 = s.s6a[j]    - ps0;
        const float ps1 = PS[j+25], hi1 = s.s6a[j+25] - ps1;
        la = fmaf(ea2.x, ps0, la); ha = fmaf(ea2.x, hi0, ha);
        la = fmaf(ea2.y, ps1, la); ha = fmaf(ea2.y, hi1, ha);
        lb = fmaf(eb2.x, ps0, lb); hb = fmaf(eb2.x, hi0, hb);
        lb = fmaf(eb2.y, ps1, lb); hb = fmaf(eb2.y, hi1, hb);
      }
      *(float4*)&s.bred[lane*4] = make_float4(la, ha, lb, hb);
    }
    __syncwarp();
    if (lane < 6){
      float acc = 0.f;
      for (int L=0;L<25;L++){
        const int g0 = (L*6)/50;
        const float4 v = *(const float4*)&s.bred[L*4];
        if (g0==lane)   acc += v.x;
        if (g0==lane-1) acc += v.y;
        if (g0==lane-3) acc += v.z;
        if (g0==lane-4) acc += v.w;
      }
      s.feat[48+lane] = acc;
    }
  }
  __syncwarp();

  // ---- FC3 (parallel over lanes + shfl reduce) ----
  {
    float a0 = 0.f, a1 = 0.f;
    if (lane < 27){
      const float fa = s.feat[lane], fb = s.feat[lane+27];
      a0 = fa*dyn[oFC3+lane]    + fb*dyn[oFC3+lane+27];
      a1 = fa*dyn[oFC3+54+lane] + fb*dyn[oFC3+54+lane+27];
    }
    #pragma unroll
    for (int off=16; off>=1; off>>=1){
      a0 += __shfl_xor_sync(FULL, a0, off);
      a1 += __shfl_xor_sync(FULL, a1, off);
    }
    if (lane == 0){
      out[(size_t)b*2]   = a0 + dyn[oFC3B];
      out[(size_t)b*2+1] = a1 + dyn[oFC3B+1];
    }
  }
}

extern "C" void kernel_launch(void* const* d_in, const int* in_sizes, int n_in,
                              void* d_out, int out_size) {
  const float* x      = (const float*)d_in[0];
  const float* we_w   = (const float*)d_in[1];
  const float* we_b   = (const float*)d_in[2];
  const float* attn_w = (const float*)d_in[3];
  const float* attn_b = (const float*)d_in[4];
  const float* c1w    = (const float*)d_in[5];
  const float* c1b    = (const float*)d_in[6];
  const float* c2w    = (const float*)d_in[7];
  const float* c2b    = (const float*)d_in[8];
  const float* c3w    = (const float*)d_in[9];
  const float* c3b    = (const float*)d_in[10];
  const float* wih    = (const float*)d_in[11];
  const float* whh    = (const float*)d_in[12];
  const float* bih    = (const float*)d_in[13];
  const float* bhh    = (const float*)d_in[14];
  const float* fc3w   = (const float*)d_in[15];
  const float* fc3b   = (const float*)d_in[16];
  float* out = (float*)d_out;

  const int B = in_sizes[0] / 1000;
  const int blocks = (B + WPB - 1) / WPB;
  cudaFuncSetAttribute(nn_fused_kernel, cudaFuncAttributeMaxDynamicSharedMemorySize, SMEM_BYTES);
  nn_fused_kernel<<<blocks, WPB*32, SMEM_BYTES>>>(x, we_w, we_b, attn_w, attn_b,
                                  c1w, c1b, c2w, c2b, c3w, c3b,
                                  wih, whh, bih, bhh, fc3w, fc3b, out, B);
}

// round 17
// speedup vs baseline: 1.1341x; 1.0184x over previous
#include <cuda_runtime.h>
#include <cuda_fp16.h>

#define FULL 0xffffffffu
typedef unsigned long long u64;
typedef unsigned int u32;

__device__ __forceinline__ float lrelu(float v){ return v > 0.f ? v : 0.1f*v; }
__device__ __forceinline__ float tanha(float v){
  float r; asm("tanh.approx.f32 %0, %1;" : "=f"(r) : "f"(v)); return r;
}
__device__ __forceinline__ float sigma(float v){
  return fmaf(tanha(0.5f*v), 0.5f, 0.5f);
}
__device__ __forceinline__ u64 pk2(float lo, float hi){
  u64 r; asm("mov.b64 %0,{%1,%2};" : "=l"(r) : "f"(lo), "f"(hi)); return r;
}
__device__ __forceinline__ float2 up2(u64 v){
  float2 r; asm("mov.b64 {%0,%1},%2;" : "=f"(r.x), "=f"(r.y) : "l"(v)); return r;
}
__device__ __forceinline__ u64 ffma2(u64 a, u64 b, u64 c){
  u64 d; asm("fma.rn.f32x2 %0,%1,%2,%3;" : "=l"(d) : "l"(a), "l"(b), "l"(c)); return d;
}
__device__ __forceinline__ u64 fadd2(u64 a, u64 b){
  u64 d; asm("add.rn.f32x2 %0,%1,%2;" : "=l"(d) : "l"(a), "l"(b)); return d;
}

// ---- dynamic smem: weights region (+LUT) then WPB per-warp workspaces ----
#define oWEW   0      // 16 rows stride 20
#define oWEB   320
#define oAW    336    // 16 rows stride 17
#define oAB    608
#define oC1W   624    // 16 rows stride 17
#define oC1B   896
#define oC2W   912    // 16 rows stride 49, [j][c*3+k]
#define oC2B   1696
#define oC3W   1712   // 16 rows stride 81, [j][c*5+k]
#define oC3B   3008
#define oWIH   3024   // 18 rows stride 20
#define oBIH   3384
#define oWHH   3404   // 18 rows stride 7
#define oBHH   3530
#define oFC3   3552   // 108
#define oFC3B  3660
#define oLUT   3664   // u16[2400] = 1200 floats
#define W_TOT  4864   // 16B-aligned

struct WS {
  float xe[800];    // embed out, flat [l*16+c]; xr[c][l] view = xe[c*50+l]
  float attn[800];  // tanh attention [l][16]; ALSO x-staging; ALSO eM overflow in D
  float x4[304];    // GRU outputs flat [l*6+h]
  float p2a[52];    // per-j prefix sums over h (inv-scaled in D)
  float p4a[52];
  float s6a[52];
  float bred[104];  // per-lane (la,ha,lb,hb) bin partials
  float feat[56];
};                   // 2220 floats

#define WPB 6
#define SMEM_FLOATS (W_TOT + WPB*2220)
#define SMEM_BYTES  (SMEM_FLOATS*4)

__global__ __launch_bounds__(WPB*32, 3) void nn_fused_kernel(
    const float* __restrict__ x,
    const float* __restrict__ we_w, const float* __restrict__ we_b,
    const float* __restrict__ attn_w, const float* __restrict__ attn_b,
    const float* __restrict__ c1w, const float* __restrict__ c1b,
    const float* __restrict__ c2w, const float* __restrict__ c2b,
    const float* __restrict__ c3w, const float* __restrict__ c3b,
    const float* __restrict__ wih, const float* __restrict__ whh,
    const float* __restrict__ bih, const float* __restrict__ bhh,
    const float* __restrict__ fc3w, const float* __restrict__ fc3b,
    float* __restrict__ out, int B)
{
  extern __shared__ float dyn[];
  const int tid = threadIdx.x;
  const int NT = WPB*32;

  // ---- cooperative weight load ----
  for (int i=tid;i<320;i+=NT)  dyn[oWEW + i] = we_w[i];
  for (int i=tid;i<256;i+=NT)  dyn[oAW  + (i>>4)*17+(i&15)] = attn_w[i];
  for (int i=tid;i<256;i+=NT)  dyn[oC1W + (i>>4)*17+(i&15)] = c1w[i];
  for (int i=tid;i<768;i+=NT)  dyn[oC2W + (i/48)*49+(i%48)] = c2w[i];
  for (int i=tid;i<1280;i+=NT) dyn[oC3W + (i/80)*81+(i%80)] = c3w[i];
  for (int i=tid;i<288;i+=NT)  dyn[oWIH + (i>>4)*20+(i&15)] = wih[i];
  for (int i=tid;i<108;i+=NT)  dyn[oWHH + (i/6)*7+(i%6)]    = whh[i];
  for (int i=tid;i<108;i+=NT)  dyn[oFC3 + i] = fc3w[i];
  {
    unsigned short* LUT = (unsigned short*)(dyn + oLUT);
    for (int i=tid;i<2400;i+=NT) LUT[i] = (unsigned short)((i/48)*16 + (i&15));
  }
  if (tid<16){ dyn[oWEB+tid]=we_b[tid]; dyn[oAB+tid]=attn_b[tid];
               dyn[oC1B+tid]=c1b[tid]; dyn[oC2B+tid]=c2b[tid]; dyn[oC3B+tid]=c3b[tid]; }
  if (tid>=32 && tid<50){ dyn[oBIH+tid-32]=bih[tid-32]; dyn[oBHH+tid-32]=bhh[tid-32]; }
  if (tid==50){ dyn[oFC3B]=fc3b[0]; dyn[oFC3B+1]=fc3b[1]; }
  __syncthreads();

  const int w    = tid >> 5;
  const int lane = tid & 31;
  WS& s = *((WS*)(dyn + W_TOT) + w);
  const unsigned short* LUT = (const unsigned short*)(dyn + oLUT);
  const int b = blockIdx.x*WPB + w;
  if (b >= B) return;

  // ---- stage x [50][20] into attn..x4 region via float4 ----
  float* xstage = s.attn;
  {
    const float4* xb4 = (const float4*)(x + (size_t)b*1000);
    float4* r4 = (float4*)xstage;
    for (int i=lane;i<250;i+=32) r4[i] = xb4[i];
  }
  __syncwarp();

  // ---- Phase A: xe[l][c] = x[l,:] . we_w[c,:] + b[c] ----
  {
    const int c = lane & 15;
    float wr[20];
    const float4* wp = (const float4*)&dyn[oWEW + c*20];
    #pragma unroll
    for (int q=0;q<5;q++){ float4 v = wp[q]; wr[4*q]=v.x; wr[4*q+1]=v.y; wr[4*q+2]=v.z; wr[4*q+3]=v.w; }
    const float bc = dyn[oWEB+c];
    for (int k=lane;k<800;k+=32){
      const int l = k >> 4;
      const float4* rp = (const float4*)&xstage[l*20];
      float acc = bc;
      #pragma unroll
      for (int q=0;q<5;q++){
        float4 v = rp[q];
        acc = fmaf(v.x, wr[4*q], acc); acc = fmaf(v.y, wr[4*q+1], acc);
        acc = fmaf(v.z, wr[4*q+2], acc); acc = fmaf(v.w, wr[4*q+3], acc);
      }
      s.xe[k] = acc;
    }
  }
  __syncwarp();

  // ---- Phase B (f32x2 + MUFU tanh): attn[l][c], pairs of l ----
  {
    const int c  = lane & 15;
    const int ph = lane >> 4;
    u64 arp[16];
    #pragma unroll
    for (int cc=0;cc<16;cc++){ float v = dyn[oAW + c*17+cc]; arp[cc] = pk2(v,v); }
    const float ab = dyn[oAB+c];
    for (int p = ph; p < 25; p += 2){
      const int l = 2*p;
      u64 accA = pk2(ab, ab), accB = 0ull;
      #pragma unroll
      for (int cc=0;cc<8;cc++){
        accA = ffma2(arp[cc],   *(const u64*)&s.xe[cc*50+l],     accA);
        accB = ffma2(arp[cc+8], *(const u64*)&s.xe[(cc+8)*50+l], accB);
      }
      float2 v = up2(fadd2(accA, accB));
      s.attn[l*16+c]    = tanha(v.x);
      s.attn[l*16+16+c] = tanha(v.y);
    }
  }
  __syncwarp();

  // ---- Phase C: GRU, branch-free inner step (all lanes compute; store predicated) ----
  {
    const int g = lane < 18 ? lane : 0;
    float wr[16];
    {
      const float4* wp = (const float4*)&dyn[oWIH + g*20];
      #pragma unroll
      for (int q=0;q<4;q++){ float4 v=wp[q]; wr[4*q]=v.x; wr[4*q+1]=v.y; wr[4*q+2]=v.z; wr[4*q+3]=v.w; }
    }
    float wh[6];
    #pragma unroll
    for (int i=0;i<6;i++) wh[i]=dyn[oWHH + g*7+i];
    const float bg  = dyn[oBIH+g];
    const float bhg = dyn[oBHH+g];
    float h0=0,h1=0,h2=0,h3=0,h4=0,h5=0, hm=0;
    #pragma unroll 2
    for (int l=0;l<50;l++){
      const float4* xp = (const float4*)&s.xe[l*16];
      float gi = bg;
      #pragma unroll
      for (int q=0;q<4;q++){
        float4 xv = xp[q];
        gi = fmaf(xv.x, wr[4*q], gi); gi = fmaf(xv.y, wr[4*q+1], gi);
        gi = fmaf(xv.z, wr[4*q+2], gi); gi = fmaf(xv.w, wr[4*q+3], gi);
      }
      float gh = bhg;
      gh = fmaf(wh[0],h0,gh); gh = fmaf(wh[1],h1,gh); gh = fmaf(wh[2],h2,gh);
      gh = fmaf(wh[3],h3,gh); gh = fmaf(wh[4],h4,gh); gh = fmaf(wh[5],h5,gh);
      const float a   = gi + gh;
      const float ar  = __shfl_sync(FULL, a,  lane);
      const float az  = __shfl_sync(FULL, a,  lane+6);
      const float gin = __shfl_sync(FULL, gi, lane+12);
      const float ghn = __shfl_sync(FULL, gh, lane+12);
      // branch-free: all lanes compute (garbage on lanes >= 6, never consumed)
      const float r = sigma(ar);
      const float z = sigma(az);
      const float n = tanha(fmaf(r, ghn, gin));
      const float hn = (1.f - z)*n + z*hm;
      hm = hn;
      if (lane < 6) s.x4[l*6+lane] = hn;   // single predicated STS
      h0=__shfl_sync(FULL,hn,0); h1=__shfl_sync(FULL,hn,1); h2=__shfl_sync(FULL,hn,2);
      h3=__shfl_sync(FULL,hn,3); h4=__shfl_sync(FULL,hn,4); h5=__shfl_sync(FULL,hn,5);
    }
  }
  __syncwarp();

  // ---- Phase E (l-split halves, 2-pass, weights hoisted per (pass,c)) ----
  {
    const int j     = lane & 15;
    const int half  = lane >> 4;
    const int lbase = half*25;
    const float b1 = dyn[oC1B+j], b2 = dyn[oC2B+j], b3 = dyn[oC3B+j];
    float xc1 = 0.f, xc2 = 0.f, xc3 = 0.f;
    #pragma unroll
    for (int P=0;P<2;P++){
      const int o0 = lbase + (P ? 13 : 0);   // pass0: 13 outputs, pass1: 12
      const int NO = P ? 12 : 13;
      float acc1[13], acc2[13], acc3[13];
      #pragma unroll
      for (int o=0;o<13;o++){ acc1[o]=0.f; acc2[o]=0.f; acc3[o]=0.f; }
      #pragma unroll 2
      for (int c=0;c<16;c++){
        const float* xr = &s.xe[c*50];
        float win[17];              // taps t = o0-2 .. o0+14 (unconditional; memory-safe)
        #pragma unroll
        for (int off=0;off<17;off++) win[off] = xr[o0 + off - 2];
        if (P==0 && half==0){ win[0]=0.f; win[1]=0.f; }              // t = -2, -1
        if (P==1 && half==1){ win[14]=0.f; win[15]=0.f; win[16]=0.f; } // t = 50, 51, 52
        const float wo  = dyn[oC1W + j*17 + c];
        const float w2a = dyn[oC2W + j*49 + c*3];
        const float w2b = dyn[oC2W + j*49 + c*3+1];
        const float w2c = dyn[oC2W + j*49 + c*3+2];
        const float w30 = dyn[oC3W + j*81 + c*5];
        const float w31 = dyn[oC3W + j*81 + c*5+1];
        const float w32 = dyn[oC3W + j*81 + c*5+2];
        const float w33 = dyn[oC3W + j*81 + c*5+3];
        const float w34 = dyn[oC3W + j*81 + c*5+4];
        #pragma unroll
        for (int o=0;o<13;o++){
          if (o >= NO) break;
          acc1[o] = fmaf(wo, win[o+2], acc1[o]);
          acc2[o] = fmaf(w2a, win[o+1], fmaf(w2b, win[o+2], fmaf(w2c, win[o+3], acc2[o])));
          float a = acc3[o];
          a = fmaf(w30, win[o],   a);
          a = fmaf(w31, win[o+1], a);
          a = fmaf(w32, win[o+2], a);
          a = fmaf(w33, win[o+3], a);
          a = fmaf(w34, win[o+4], a);
          acc3[o] = a;
        }
      }
      #pragma unroll
      for (int o=0;o<13;o++){
        if (o >= NO) break;
        const int l = o0 + o;
        const float v1 = acc1[o] + b1;
        const float v2 = acc2[o] + b2;
        const float v3 = acc3[o] + b3;
        const int i1 = j*50+l, i2 = (16+j)*50+l, i3 = (32+j)*50+l;
        xc1 = fmaf(lrelu(v1), s.attn[LUT[i1]], xc1);
        xc2 = fmaf(lrelu(v2), s.attn[LUT[i2]], xc2);
        xc3 = fmaf(lrelu(v3), s.attn[LUT[i3]], xc3);
      }
    }
    xc1 += __shfl_xor_sync(FULL, xc1, 16);
    xc2 += __shfl_xor_sync(FULL, xc2, 16);
    xc3 += __shfl_xor_sync(FULL, xc3, 16);
    if (half==0){ s.feat[j]=xc1; s.feat[16+j]=xc2; s.feat[32+j]=xc3; }
  }
  __syncwarp();

  // ---- Phase D (fused): score cache in xe region as half2, inv folded into PS ----
  {
    u32* eM = (u32*)s.xe;      // [25][53] u32; 1325 u32 < xe+attn (1600)
    if (lane < 25){
      float p2ja, p4ja, s6ja, p2jb, p4jb, s6jb;
      {
        const float2 a0=*(const float2*)&s.x4[lane*6], a1=*(const float2*)&s.x4[lane*6+2], a2=*(const float2*)&s.x4[lane*6+4];
        p2ja = a0.x+a0.y; p4ja = p2ja + a1.x+a1.y; s6ja = p4ja + a2.x+a2.y;
        const int jb6 = (lane+25)*6;
        const float2 b0=*(const float2*)&s.x4[jb6], b1=*(const float2*)&s.x4[jb6+2], b2=*(const float2*)&s.x4[jb6+4];
        p2jb = b0.x+b0.y; p4jb = p2jb + b1.x+b1.y; s6jb = p4jb + b2.x+b2.y;
      }
      const int ja = lane, jb = lane+25;
      float xra[6], xrb[6];
      #pragma unroll
      for (int h=0;h<6;h++){ xra[h]=s.x4[h*50+ja]; xrb[h]=s.x4[h*50+jb]; }
      float csa=0.f, csb=0.f;
      for (int i=0;i<50;i++){
        const float2 p0 = *(const float2*)&s.x4[i*6];
        const float2 p1 = *(const float2*)&s.x4[i*6+2];
        const float2 p2 = *(const float2*)&s.x4[i*6+4];
        float sa = p0.x*xra[0] + p0.y*xra[1];
        sa = fmaf(p1.x,xra[2], fmaf(p1.y,xra[3], sa));
        sa = fmaf(p2.x,xra[4], fmaf(p2.y,xra[5], sa));
        float sb = p0.x*xrb[0] + p0.y*xrb[1];
        sb = fmaf(p1.x,xrb[2], fmaf(p1.y,xrb[3], sb));
        sb = fmaf(p2.x,xrb[4], fmaf(p2.y,xrb[5], sb));
        const float ea = __expf(sa*(1.f/6.f));
        const float eb = __expf(sb*(1.f/6.f));
        csa += ea; csb += eb;
        __half2 hp = __floats2half2_rn(ea, eb);
        eM[lane*53+i] = *(u32*)&hp;
      }
      const float iva = __fdividef(1.f, csa);
      const float ivb = __fdividef(1.f, csb);
      s.p2a[ja] = p2ja*iva; s.p4a[ja] = p4ja*iva; s.s6a[ja] = s6ja*iva;
      s.p2a[jb] = p2jb*ivb; s.p4a[jb] = p4jb*ivb; s.s6a[jb] = s6jb*ivb;
    }
    __syncwarp();
    if (lane < 25){
      const int ia = lane, ib = lane+25;
      const int m = (ia*6) % 50;
      const float* PS = (m==48) ? s.p2a : (m==46) ? s.p4a : s.s6a;
      float la=0.f, ha=0.f, lb=0.f, hb=0.f;
      for (int j=0;j<25;j++){
        const u32 pa = eM[j*53+ia];
        const u32 pb = eM[j*53+ib];
        const float2 ea2 = __half22float2(*(const __half2*)&pa);
        const float2 eb2 = __half22float2(*(const __half2*)&pb);
        const float ps0 = PS[j],    hi0 = s.s6a[j]    - ps0;
        const float ps1 = PS[j+25], hi1 = s.s6a[j+25] - ps1;
        la = fmaf(ea2.x, ps0, la); ha = fmaf(ea2.x, hi0, ha);
        la = fmaf(ea2.y, ps1, la); ha = fmaf(ea2.y, hi1, ha);
        lb = fmaf(eb2.x, ps0, lb); hb = fmaf(eb2.x, hi0, hb);
        lb = fmaf(eb2.y, ps1, lb); hb = fmaf(eb2.y, hi1, hb);
      }
      *(float4*)&s.bred[lane*4] = make_float4(la, ha, lb, hb);
    }
    __syncwarp();
    if (lane < 6){
      float acc = 0.f;
      for (int L=0;L<25;L++){
        const int g0 = (L*6)/50;
        const float4 v = *(const float4*)&s.bred[L*4];
        if (g0==lane)   acc += v.x;
        if (g0==lane-1) acc += v.y;
        if (g0==lane-3) acc += v.z;
        if (g0==lane-4) acc += v.w;
      }
      s.feat[48+lane] = acc;
    }
  }
  __syncwarp();

  // ---- FC3 (parallel over lanes + shfl reduce) ----
  {
    float a0 = 0.f, a1 = 0.f;
    if (lane < 27){
      const float fa = s.feat[lane], fb = s.feat[lane+27];
      a0 = fa*dyn[oFC3+lane]    + fb*dyn[oFC3+lane+27];
      a1 = fa*dyn[oFC3+54+lane] + fb*dyn[oFC3+54+lane+27];
    }
    #pragma unroll
    for (int off=16; off>=1; off>>=1){
      a0 += __shfl_xor_sync(FULL, a0, off);
      a1 += __shfl_xor_sync(FULL, a1, off);
    }
    if (lane == 0){
      out[(size_t)b*2]   = a0 + dyn[oFC3B];
      out[(size_t)b*2+1] = a1 + dyn[oFC3B+1];
    }
  }
}

extern "C" void kernel_launch(void* const* d_in, const int* in_sizes, int n_in,
                              void* d_out, int out_size) {
  const float* x      = (const float*)d_in[0];
  const float* we_w   = (const float*)d_in[1];
  const float* we_b   = (const float*)d_in[2];
  const float* attn_w = (const float*)d_in[3];
  const float* attn_b = (const float*)d_in[4];
  const float* c1w    = (const float*)d_in[5];
  const float* c1b    = (const float*)d_in[6];
  const float* c2w    = (const float*)d_in[7];
  const float* c2b    = (const float*)d_in[8];
  const float* c3w    = (const float*)d_in[9];
  const float* c3b    = (const float*)d_in[10];
  const float* wih    = (const float*)d_in[11];
  const float* whh    = (const float*)d_in[12];
  const float* bih    = (const float*)d_in[13];
  const float* bhh    = (const float*)d_in[14];
  const float* fc3w   = (const float*)d_in[15];
  const float* fc3b   = (const float*)d_in[16];
  float* out = (float*)d_out;

  const int B = in_sizes[0] / 1000;
  const int blocks = (B + WPB - 1) / WPB;
  cudaFuncSetAttribute(nn_fused_kernel, cudaFuncAttributeMaxDynamicSharedMemorySize, SMEM_BYTES);
  nn_fused_kernel<<<blocks, WPB*32, SMEM_BYTES>>>(x, we_w, we_b, attn_w, attn_b,
                                  c1w, c1b, c2w, c2b, c3w, c3b,
                                  wih, whh, bih, bhh, fc3w, fc3b, out, B);
}